// round 1
// baseline (speedup 1.0000x reference)
#include <cuda_runtime.h>
#include <cuda_bf16.h>

#define NB 16
#define NC 64
#define HH 64
#define WW 64
#define HW 4096      // 64*64
#define HWP 1024     // 32*32
#define CK 8         // C/8
#define CV 32        // C/2

// Scratch (device globals; no allocation allowed)
__device__ float d_theta[NB * CK * HW];        // [b][k][n]
__device__ float d_phi[NB * CK * HWP];         // [b][k][m]
__device__ float d_gt[NB * HWP * CV];          // [b][m][c]   (transposed g)
__device__ float d_ot[NB * HW * CV];           // [b][n][c]   (transposed o)

// ---------------------------------------------------------------------------
// Kernel A: 1x1 conv projections theta/phi/g + 2x2 maxpool for phi/g.
// grid (32, 16): blockIdx.x = pooled row hc (rows 2hc, 2hc+1), blockIdx.y = b.
// 128 threads: t = dy*64 + w  (2 rows x 64 cols of pixels).
// ---------------------------------------------------------------------------
__global__ __launch_bounds__(128) void proj_kernel(
    const float* __restrict__ x,
    const float* __restrict__ w_theta,
    const float* __restrict__ w_phi,
    const float* __restrict__ w_g)
{
    __shared__ float w_s[48 * 64];      // rows: 0-7 theta, 8-15 phi, 16-47 g
    __shared__ float x_s[64 * 128];     // x tile; reused as pooling staging [128][41]

    int b = blockIdx.y;
    int hc = blockIdx.x;
    int t = threadIdx.x;

    for (int i = t; i < 8 * 64; i += 128)  w_s[i]           = w_theta[i];
    for (int i = t; i < 8 * 64; i += 128)  w_s[8 * 64 + i]  = w_phi[i];
    for (int i = t; i < 32 * 64; i += 128) w_s[16 * 64 + i] = w_g[i];

    // Rows 2hc,2hc+1 are 128 contiguous floats per channel (W=64).
    const float* xb = x + ((size_t)b * NC) * HW + (size_t)hc * 128;
    for (int c = 0; c < 64; c++) x_s[c * 128 + t] = xb[(size_t)c * HW + t];
    __syncthreads();

    float acc[48];
#pragma unroll
    for (int k = 0; k < 48; k++) acc[k] = 0.f;
    for (int c = 0; c < 64; c++) {
        float xv = x_s[c * 128 + t];
#pragma unroll
        for (int k = 0; k < 48; k++) acc[k] += w_s[k * 64 + c] * xv;
    }

    // theta: pixel index p = (2hc+dy)*64 + w = hc*128 + t  (coalesced)
    {
        int p = hc * 128 + t;
        float* th = d_theta + (size_t)b * CK * HW;
#pragma unroll
        for (int k = 0; k < 8; k++) th[k * HW + p] = acc[k];
    }
    __syncthreads();   // everyone done with x_s before reuse

    // Stage phi(8)+g(32) per pixel for pooling: pg[t][k], row stride 41 (no conflicts)
#pragma unroll
    for (int k = 0; k < 40; k++) x_s[t * 41 + k] = acc[8 + k];
    __syncthreads();

    if (t < 64) {
        int wc = t;                 // pooled column 0..63? no: 0..31 valid
        if (wc < 32) {
            int r0 = 2 * wc, r1 = 2 * wc + 1, r2 = 64 + 2 * wc, r3 = 65 + 2 * wc;
            int m = hc * 32 + wc;
#pragma unroll
            for (int k = 0; k < 40; k++) {
                float v = fmaxf(fmaxf(x_s[r0 * 41 + k], x_s[r1 * 41 + k]),
                                fmaxf(x_s[r2 * 41 + k], x_s[r3 * 41 + k]));
                if (k < 8)
                    d_phi[((size_t)b * CK + k) * HWP + m] = v;
                else
                    d_gt[((size_t)b * HWP + m) * CV + (k - 8)] = v;
            }
        }
    }
}

// ---------------------------------------------------------------------------
// Kernel B: fused attention. o[b][n][c] = sum_m softmax_m(theta.phi) * g[c][m]
// grid (8, 16): blockIdx.x = query tile (512 queries), blockIdx.y = b.
// 512 threads = 16 warps; warp handles 32 queries (8 groups of 4).
// Lane = value channel (CV=32). No row-max needed: |score| <~ 25 -> exp fits fp32.
// Dynamic smem: phi[8][1024] | g_t[1024][32] | theta[512][8] | e-stage[16][4][32]
// ---------------------------------------------------------------------------
__global__ __launch_bounds__(512) void attn_kernel()
{
    extern __shared__ float sm[];
    float* phi_s = sm;                       // 8192
    float* g_s   = sm + 8192;                // 32768
    float* th_s  = sm + 8192 + 32768;        // 4096
    float* e_s   = th_s + 4096;              // 2048

    int b = blockIdx.y;
    int q0 = blockIdx.x * 512;
    int tid = threadIdx.x, lane = tid & 31, wid = tid >> 5;

    for (int i = tid; i < 8192; i += 512)
        phi_s[i] = d_phi[(size_t)b * (CK * HWP) + i];
    for (int i = tid; i < 32768; i += 512)
        g_s[i] = d_gt[(size_t)b * (HWP * CV) + i];
    for (int i = tid; i < 4096; i += 512) {
        int k = i >> 9, q = i & 511;         // coalesced over q
        th_s[q * 8 + k] = d_theta[((size_t)b * CK + k) * HW + q0 + q];
    }
    __syncthreads();

    float* es = e_s + wid * 128;             // this warp's 4x32 exp stage

    for (int g4 = 0; g4 < 8; g4++) {
        int qb = wid * 32 + g4 * 4;          // local query base within tile
        float th[4][8];
#pragma unroll
        for (int q = 0; q < 4; q++)
#pragma unroll
            for (int k = 0; k < 8; k++) th[q][k] = th_s[(qb + q) * 8 + k];

        float acc[4]  = {0.f, 0.f, 0.f, 0.f};
        float denp[4] = {0.f, 0.f, 0.f, 0.f};

        for (int mc = 0; mc < 32; mc++) {
            int m = mc * 32 + lane;
            float ph[8];
#pragma unroll
            for (int k = 0; k < 8; k++) ph[k] = phi_s[k * 1024 + m];
#pragma unroll
            for (int q = 0; q < 4; q++) {
                float s = 0.f;
#pragma unroll
                for (int k = 0; k < 8; k++) s += th[q][k] * ph[k];
                float e = __expf(s);
                denp[q] += e;
                es[q * 32 + lane] = e;
            }
            __syncwarp();
            const float* gp = g_s + mc * 32 * 32 + lane;
#pragma unroll
            for (int j = 0; j < 32; j++) {
                float gv = gp[j * 32];
#pragma unroll
                for (int q = 0; q < 4; q++) acc[q] += es[q * 32 + j] * gv;
            }
            __syncwarp();
        }

#pragma unroll
        for (int q = 0; q < 4; q++) {
            float d = denp[q];
#pragma unroll
            for (int o = 16; o > 0; o >>= 1) d += __shfl_xor_sync(0xffffffffu, d, o);
            int n = q0 + qb + q;
            d_ot[((size_t)b * HW + n) * CV + lane] = acc[q] / d;   // coalesced
        }
    }
}

// ---------------------------------------------------------------------------
// Kernel C: out = gamma * (w_o @ o) + x.
// grid (16, 16): blockIdx.x = pixel tile (256 pixels), blockIdx.y = b.
// 256 threads, one pixel each, 64 channel accumulators in registers.
// ---------------------------------------------------------------------------
__global__ __launch_bounds__(256) void out_kernel(
    const float* __restrict__ x,
    const float* __restrict__ w_o,
    const float* __restrict__ gamma_p,
    float* __restrict__ out)
{
    __shared__ float wo_s[64 * 32];          // 8KB
    __shared__ float o_s[256 * 33];          // padded rows, no conflicts

    int b = blockIdx.y;
    int p0 = blockIdx.x * 256;
    int t = threadIdx.x;
    float gamma = *gamma_p;

    for (int i = t; i < 2048; i += 256) wo_s[i] = w_o[i];
    for (int i = t; i < 8192; i += 256) {
        int pp = i >> 5, c = i & 31;
        o_s[pp * 33 + c] = d_ot[((size_t)b * HW + p0) * CV + i];   // coalesced
    }
    __syncthreads();

    float acc[64];
#pragma unroll
    for (int ch = 0; ch < 64; ch++) acc[ch] = 0.f;
    for (int c = 0; c < 32; c++) {
        float ov = o_s[t * 33 + c];
#pragma unroll
        for (int ch = 0; ch < 64; ch++) acc[ch] += wo_s[ch * 32 + c] * ov;
    }

    int p = p0 + t;
    const float* xb = x + (size_t)b * NC * HW;
    float* ob = out + (size_t)b * NC * HW;
#pragma unroll
    for (int ch = 0; ch < 64; ch++)
        ob[(size_t)ch * HW + p] = gamma * acc[ch] + xb[(size_t)ch * HW + p];
}

// ---------------------------------------------------------------------------
extern "C" void kernel_launch(void* const* d_in, const int* in_sizes, int n_in,
                              void* d_out, int out_size)
{
    const float* x       = (const float*)d_in[0];
    const float* w_theta = (const float*)d_in[1];
    const float* w_phi   = (const float*)d_in[2];
    const float* w_g     = (const float*)d_in[3];
    const float* w_o     = (const float*)d_in[4];
    const float* gamma_p = (const float*)d_in[5];
    float* out = (float*)d_out;

    proj_kernel<<<dim3(32, 16), 128>>>(x, w_theta, w_phi, w_g);

    size_t smemB = (size_t)(8192 + 32768 + 4096 + 2048) * sizeof(float);  // 184KB
    cudaFuncSetAttribute(attn_kernel, cudaFuncAttributeMaxDynamicSharedMemorySize,
                         (int)smemB);
    attn_kernel<<<dim3(8, 16), 512, smemB>>>();

    out_kernel<<<dim3(16, 16), 256>>>(x, w_o, gamma_p, out);
}

// round 3
// speedup vs baseline: 1.3685x; 1.3685x over previous
#include <cuda_runtime.h>
#include <cuda_bf16.h>
#include <cstdint>

#define NB 16
#define NC 64
#define HW 4096      // 64*64
#define HWP 1024     // 32*32
#define CK 8         // C/8
#define CV 32        // C/2

// Scratch (device globals; no allocation allowed)
__device__ float d_theta[NB * CK * HW];                 // [b][k][n] fp32
__device__ __nv_bfloat16 d_phih[NB * HWP * CK];         // [b][m][k] hi
__device__ __nv_bfloat16 d_phil[NB * HWP * CK];         // [b][m][k] lo
__device__ __nv_bfloat16 d_gh[NB * CV * HWP];           // [b][c][m] hi
__device__ __nv_bfloat16 d_gl[NB * CV * HWP];           // [b][c][m] lo
__device__ float d_ot[NB * HW * CV];                    // [b][n][c]

// ---------------------------------------------------------------------------
__device__ __forceinline__ uint32_t pack2(float a, float b) {
    __nv_bfloat162 t = __floats2bfloat162_rn(a, b);
    return *(uint32_t*)&t;
}
// split (a,b) -> packed hi pair, packed lo (residual) pair
__device__ __forceinline__ void split2(float a, float b, uint32_t& hi, uint32_t& lo) {
    __nv_bfloat16 ha = __float2bfloat16_rn(a), hb = __float2bfloat16_rn(b);
    hi = ((uint32_t)*(unsigned short*)&hb << 16) | (uint32_t)*(unsigned short*)&ha;
    lo = pack2(a - __bfloat162float(ha), b - __bfloat162float(hb));
}
__device__ __forceinline__ void split1(float v, __nv_bfloat16& h, __nv_bfloat16& l) {
    h = __float2bfloat16_rn(v);
    l = __float2bfloat16_rn(v - __bfloat162float(h));
}

#define MMA16816(c0,c1,c2,c3,a0,a1,a2,a3,b0,b1) \
    asm volatile("mma.sync.aligned.m16n8k16.row.col.f32.bf16.bf16.f32 " \
        "{%0,%1,%2,%3}, {%4,%5,%6,%7}, {%8,%9}, {%0,%1,%2,%3};" \
        : "+f"(c0),"+f"(c1),"+f"(c2),"+f"(c3) \
        : "r"(a0),"r"(a1),"r"(a2),"r"(a3),"r"(b0),"r"(b1))

// ---------------------------------------------------------------------------
// Kernel A: 1x1 conv projections + 2x2 maxpool; emits theta fp32 and
// split-bf16 phi/g in attention-friendly layouts.
// grid (32, 2, 16): x = pooled row hc, y = output-channel half, z = batch.
// half 0: theta(8) + phi(8) + g(0..7);  half 1: g(8..31).
// ---------------------------------------------------------------------------
__global__ __launch_bounds__(128) void proj_kernel(
    const float* __restrict__ x,
    const float* __restrict__ w_theta,
    const float* __restrict__ w_phi,
    const float* __restrict__ w_g)
{
    __shared__ float w_s[24 * 64];      // 6KB
    __shared__ float x_s[64 * 128];     // 32KB; reused as pooling staging

    const int b = blockIdx.z;
    const int hc = blockIdx.x;
    const int half = blockIdx.y;
    const int t = threadIdx.x;

    for (int i = t; i < 24 * 64; i += 128) {
        int r = half * 24 + (i >> 6), c = i & 63;
        float wv = (r < 8) ? w_theta[r * 64 + c]
                 : (r < 16) ? w_phi[(r - 8) * 64 + c]
                            : w_g[(r - 16) * 64 + c];
        w_s[i] = wv;
    }

    const float* xb = x + ((size_t)b * NC) * HW + (size_t)hc * 128;
    for (int c = 0; c < 64; c++) x_s[c * 128 + t] = xb[(size_t)c * HW + t];
    __syncthreads();

    float acc[24];
#pragma unroll
    for (int k = 0; k < 24; k++) acc[k] = 0.f;
    for (int c = 0; c < 64; c++) {
        float xv = x_s[c * 128 + t];
#pragma unroll
        for (int k = 0; k < 24; k++) acc[k] += w_s[k * 64 + c] * xv;
    }

    if (half == 0) {
        int p = hc * 128 + t;
        float* th = d_theta + (size_t)b * CK * HW;
#pragma unroll
        for (int k = 0; k < 8; k++) th[k * HW + p] = acc[k];
    }
    __syncthreads();

    // stage pooled channels: half0 -> rows 8..23 (16), half1 -> rows 24..47 (24)
    const int nst = half ? 24 : 16;
    const int off = half ? 0 : 8;
    for (int k = 0; k < nst; k++) x_s[t * 25 + k] = acc[off + k];
    __syncthreads();

    if (t < 32) {
        int r0 = 2 * t, r1 = 2 * t + 1, r2 = 64 + 2 * t, r3 = 65 + 2 * t;
        int m = hc * 32 + t;
        for (int k = 0; k < nst; k++) {
            float v = fmaxf(fmaxf(x_s[r0 * 25 + k], x_s[r1 * 25 + k]),
                            fmaxf(x_s[r2 * 25 + k], x_s[r3 * 25 + k]));
            int kk = half ? (24 + k) : (8 + k);   // row in 48-channel space
            __nv_bfloat16 h, l;
            split1(v, h, l);
            if (kk < 16) {                        // phi channel kk-8
                size_t o = ((size_t)b * HWP + m) * CK + (kk - 8);
                d_phih[o] = h; d_phil[o] = l;
            } else {                              // g channel kk-16
                size_t o = ((size_t)b * CV + (kk - 16)) * HWP + m;
                d_gh[o] = h; d_gl[o] = l;
            }
        }
    }
}

// ---------------------------------------------------------------------------
// Kernel B: HMMA flash attention, split-bf16 (fp32-accurate).
// grid (32, 16): blockIdx.x = 128-query tile, blockIdx.y = b. 256 threads = 8 warps.
// Warp handles 16 queries; loops all 1024 keys in 8-key steps, all in regs.
// smem: phi_h 16KB | phi_l 16KB | g_h 32x2064B | g_l 32x2064B  = 164864 B
// ---------------------------------------------------------------------------
#define PHI_H 0
#define PHI_L 16384
#define G_H   32768
#define G_L   98816
#define GSTRB 2064
#define SMEM_ATTN 164864

__global__ __launch_bounds__(256) void attn_mma_kernel()
{
    extern __shared__ char smem[];
    const int tid = threadIdx.x;
    const int lane = tid & 31;
    const int w = tid >> 5;
    const int gid = lane >> 2;     // group id 0..7
    const int tig = lane & 3;      // thread in group
    const int b = blockIdx.y;
    const int q0 = blockIdx.x * 128;

    // fill phi planes (contiguous copy)
    {
        const uint4* ph = (const uint4*)(d_phih + (size_t)b * HWP * CK);
        const uint4* pl = (const uint4*)(d_phil + (size_t)b * HWP * CK);
        uint4* sh = (uint4*)(smem + PHI_H);
        uint4* sl = (uint4*)(smem + PHI_L);
        for (int i = tid; i < 1024; i += 256) { sh[i] = ph[i]; sl[i] = pl[i]; }
    }
    // fill g planes (32 rows x 2048B, padded stride 2064B)
    for (int i = tid; i < 4096; i += 256) {
        int c = i >> 7, j = i & 127;
        *(uint4*)(smem + G_H + c * GSTRB + j * 16) =
            *(const uint4*)(d_gh + ((size_t)b * CV + c) * HWP + j * 8);
        *(uint4*)(smem + G_L + c * GSTRB + j * 16) =
            *(const uint4*)(d_gl + ((size_t)b * CV + c) * HWP + j * 8);
    }

    // theta A fragments (constant across key loop)
    const int qb = q0 + w * 16;
    const float* th = d_theta + (size_t)b * CK * HW;
    float t00 = th[(2 * tig) * HW + qb + gid];
    float t01 = th[(2 * tig + 1) * HW + qb + gid];
    float t10 = th[(2 * tig) * HW + qb + gid + 8];
    float t11 = th[(2 * tig + 1) * HW + qb + gid + 8];
    uint32_t ah0, al0, ah1, al1;
    split2(t00, t01, ah0, al0);
    split2(t10, t11, ah1, al1);
    __syncthreads();

    float o[4][4];
#pragma unroll
    for (int nf = 0; nf < 4; nf++)
#pragma unroll
        for (int j = 0; j < 4; j++) o[nf][j] = 0.f;
    float den0 = 0.f, den1 = 0.f;

    const uint32_t phi_off = gid * 16 + tig * 4;
    const uint32_t g_row = gid * GSTRB;

#pragma unroll 2
    for (int m0 = 0; m0 < 1024; m0 += 8) {
        uint32_t bh = *(uint32_t*)(smem + PHI_H + m0 * 16 + phi_off);
        uint32_t bl = *(uint32_t*)(smem + PHI_L + m0 * 16 + phi_off);
        float s0 = 0.f, s1 = 0.f, s2 = 0.f, s3 = 0.f;
        MMA16816(s0, s1, s2, s3, ah0, ah1, al0, al1, bh, bh);
        MMA16816(s0, s1, s2, s3, ah0, ah1, al0, al1, bl, bl);

        float e0 = __expf(s0), e1 = __expf(s1), e2 = __expf(s2), e3 = __expf(s3);
        den0 += e0 + e1;
        den1 += e2 + e3;
        uint32_t Eh0, El0, Eh1, El1;
        split2(e0, e1, Eh0, El0);
        split2(e2, e3, Eh1, El1);

        const uint32_t mo = (m0 + 2 * tig) * 2 + g_row;
#pragma unroll
        for (int nf = 0; nf < 4; nf++) {
            uint32_t gh_ = *(uint32_t*)(smem + G_H + nf * 8 * GSTRB + mo);
            uint32_t gl_ = *(uint32_t*)(smem + G_L + nf * 8 * GSTRB + mo);
            MMA16816(o[nf][0], o[nf][1], o[nf][2], o[nf][3],
                     Eh0, Eh1, El0, El1, gh_, gh_);
            MMA16816(o[nf][0], o[nf][1], o[nf][2], o[nf][3],
                     Eh0, Eh1, El0, El1, gl_, gl_);
        }
    }

    // denominator: reduce over the 4 lanes sharing each query row
    den0 += __shfl_xor_sync(0xffffffffu, den0, 1);
    den0 += __shfl_xor_sync(0xffffffffu, den0, 2);
    den1 += __shfl_xor_sync(0xffffffffu, den1, 1);
    den1 += __shfl_xor_sync(0xffffffffu, den1, 2);
    float i0 = 1.f / den0, i1 = 1.f / den1;

    float* base = d_ot + ((size_t)b * HW + qb + gid) * CV;
#pragma unroll
    for (int nf = 0; nf < 4; nf++) {
        int c = nf * 8 + 2 * tig;
        float2 v0 = make_float2(o[nf][0] * i0, o[nf][1] * i0);
        float2 v1 = make_float2(o[nf][2] * i1, o[nf][3] * i1);
        *(float2*)(base + c) = v0;
        *(float2*)(base + 8 * CV + c) = v1;
    }
}

// ---------------------------------------------------------------------------
// Kernel C: out = gamma * (w_o @ o) + x.
// ---------------------------------------------------------------------------
__global__ __launch_bounds__(256) void out_kernel(
    const float* __restrict__ x,
    const float* __restrict__ w_o,
    const float* __restrict__ gamma_p,
    float* __restrict__ out)
{
    __shared__ float wo_s[64 * 32];
    __shared__ float o_s[256 * 33];

    int b = blockIdx.y;
    int p0 = blockIdx.x * 256;
    int t = threadIdx.x;
    float gamma = *gamma_p;

    for (int i = t; i < 2048; i += 256) wo_s[i] = w_o[i];
    for (int i = t; i < 8192; i += 256) {
        int pp = i >> 5, c = i & 31;
        o_s[pp * 33 + c] = d_ot[((size_t)b * HW + p0) * CV + i];
    }
    __syncthreads();

    float acc[64];
#pragma unroll
    for (int ch = 0; ch < 64; ch++) acc[ch] = 0.f;
    for (int c = 0; c < 32; c++) {
        float ov = o_s[t * 33 + c];
#pragma unroll
        for (int ch = 0; ch < 64; ch++) acc[ch] += wo_s[ch * 32 + c] * ov;
    }

    int p = p0 + t;
    const float* xb = x + (size_t)b * NC * HW;
    float* ob = out + (size_t)b * NC * HW;
#pragma unroll
    for (int ch = 0; ch < 64; ch++)
        ob[(size_t)ch * HW + p] = gamma * acc[ch] + xb[(size_t)ch * HW + p];
}

// ---------------------------------------------------------------------------
extern "C" void kernel_launch(void* const* d_in, const int* in_sizes, int n_in,
                              void* d_out, int out_size)
{
    const float* x       = (const float*)d_in[0];
    const float* w_theta = (const float*)d_in[1];
    const float* w_phi   = (const float*)d_in[2];
    const float* w_g     = (const float*)d_in[3];
    const float* w_o     = (const float*)d_in[4];
    const float* gamma_p = (const float*)d_in[5];
    float* out = (float*)d_out;

    proj_kernel<<<dim3(32, 2, 16), 128>>>(x, w_theta, w_phi, w_g);

    cudaFuncSetAttribute(attn_mma_kernel, cudaFuncAttributeMaxDynamicSharedMemorySize,
                         SMEM_ATTN);
    attn_mma_kernel<<<dim3(32, 16), 256, SMEM_ATTN>>>();

    out_kernel<<<dim3(16, 16), 256>>>(x, w_o, gamma_p, out);
}

// round 7
// speedup vs baseline: 1.5207x; 1.1112x over previous
#include <cuda_runtime.h>
#include <cuda_bf16.h>
#include <cstdint>

#define NB 16
#define NC 64
#define HW 4096      // 64*64
#define HWP 1024     // 32*32
#define CK 8         // C/8
#define CV 32        // C/2

// Scratch (device globals; no allocation allowed)
__device__ float d_theta[NB * CK * HW];                 // [b][k][n] fp32
__device__ __nv_bfloat16 d_phih[NB * HWP * CK];         // [b][m][k] hi
__device__ __nv_bfloat16 d_phil[NB * HWP * CK];         // [b][m][k] lo
__device__ __nv_bfloat16 d_gh[NB * CV * HWP];           // [b][c][m] hi
__device__ __nv_bfloat16 d_gl[NB * CV * HWP];           // [b][c][m] lo
__device__ float d_ot[NB * HW * CV];                    // [b][n][c]

// ---------------------------------------------------------------------------
__device__ __forceinline__ uint32_t pack2(float a, float b) {
    __nv_bfloat162 t = __floats2bfloat162_rn(a, b);
    return *(uint32_t*)&t;
}
// split (a,b) -> packed hi pair, packed lo (residual) pair
__device__ __forceinline__ void split2(float a, float b, uint32_t& hi, uint32_t& lo) {
    __nv_bfloat16 ha = __float2bfloat16_rn(a), hb = __float2bfloat16_rn(b);
    hi = ((uint32_t)*(unsigned short*)&hb << 16) | (uint32_t)*(unsigned short*)&ha;
    lo = pack2(a - __bfloat162float(ha), b - __bfloat162float(hb));
}
__device__ __forceinline__ void split1(float v, __nv_bfloat16& h, __nv_bfloat16& l) {
    h = __float2bfloat16_rn(v);
    l = __float2bfloat16_rn(v - __bfloat162float(h));
}

#define MMA16816(c0,c1,c2,c3,a0,a1,a2,a3,b0,b1) \
    asm volatile("mma.sync.aligned.m16n8k16.row.col.f32.bf16.bf16.f32 " \
        "{%0,%1,%2,%3}, {%4,%5,%6,%7}, {%8,%9}, {%0,%1,%2,%3};" \
        : "+f"(c0),"+f"(c1),"+f"(c2),"+f"(c3) \
        : "r"(a0),"r"(a1),"r"(a2),"r"(a3),"r"(b0),"r"(b1))

// ---------------------------------------------------------------------------
// Kernel A: 1x1 conv projections + 2x2 maxpool; 2 pixels per thread.
// grid (16, 2, 16): x = 256-pixel tile (4 image rows), y = channel half, z = b.
// half 0: theta(8) + phi(8) + g(0..7);  half 1: g(8..31).
// ---------------------------------------------------------------------------
__global__ __launch_bounds__(128) void proj_kernel(
    const float* __restrict__ x,
    const float* __restrict__ w_theta,
    const float* __restrict__ w_phi,
    const float* __restrict__ w_g)
{
    __shared__ float w_s[24 * 64];      // 6KB
    __shared__ float x_s[64 * 256];     // 64KB; reused as pooling staging

    const int b = blockIdx.z;
    const int hc = blockIdx.x;          // 0..15, covers image rows 4hc..4hc+3
    const int half = blockIdx.y;
    const int t = threadIdx.x;

    for (int i = t; i < 24 * 64; i += 128) {
        int r = half * 24 + (i >> 6), c = i & 63;
        float wv = (r < 8) ? w_theta[r * 64 + c]
                 : (r < 16) ? w_phi[(r - 8) * 64 + c]
                            : w_g[(r - 16) * 64 + c];
        w_s[i] = wv;
    }

    const float* xb = x + ((size_t)b * NC) * HW + (size_t)hc * 256;
#pragma unroll 8
    for (int c = 0; c < 64; c++)
        *(float2*)&x_s[c * 256 + 2 * t] = *(const float2*)&xb[(size_t)c * HW + 2 * t];
    __syncthreads();

    float acc0[24], acc1[24];
#pragma unroll
    for (int k = 0; k < 24; k++) { acc0[k] = 0.f; acc1[k] = 0.f; }
    for (int c = 0; c < 64; c++) {
        float x0 = x_s[c * 256 + 2 * t];
        float x1 = x_s[c * 256 + 2 * t + 1];
#pragma unroll
        for (int k = 0; k < 24; k++) {
            float wv = w_s[k * 64 + c];
            acc0[k] += wv * x0;
            acc1[k] += wv * x1;
        }
    }

    if (half == 0) {
        int p = hc * 256 + 2 * t;
        float* th = d_theta + (size_t)b * CK * HW;
#pragma unroll
        for (int k = 0; k < 8; k++)
            *(float2*)&th[k * HW + p] = make_float2(acc0[k], acc1[k]);
    }
    __syncthreads();

    // stage pooled channels: half0 -> rows 8..23 (16), half1 -> rows 24..47 (24)
    const int nst = half ? 24 : 16;
    const int off = half ? 0 : 8;
    for (int k = 0; k < nst; k++) {
        x_s[(2 * t) * 25 + k]     = acc0[off + k];
        x_s[(2 * t + 1) * 25 + k] = acc1[off + k];
    }
    __syncthreads();

    if (t < 64) {
        int sub = t >> 5, wc = t & 31;
        int p00 = (2 * sub) * 64 + 2 * wc;      // local pixel indices
        int p01 = p00 + 1, p10 = p00 + 64, p11 = p00 + 65;
        int m = (2 * hc + sub) * 32 + wc;       // pooled index
        for (int k = 0; k < nst; k++) {
            float v = fmaxf(fmaxf(x_s[p00 * 25 + k], x_s[p01 * 25 + k]),
                            fmaxf(x_s[p10 * 25 + k], x_s[p11 * 25 + k]));
            int kk = half ? (24 + k) : (8 + k);
            __nv_bfloat16 h, l;
            split1(v, h, l);
            if (kk < 16) {
                size_t o = ((size_t)b * HWP + m) * CK + (kk - 8);
                d_phih[o] = h; d_phil[o] = l;
            } else {
                size_t o = ((size_t)b * CV + (kk - 16)) * HWP + m;
                d_gh[o] = h; d_gl[o] = l;
            }
        }
    }
}

// ---------------------------------------------------------------------------
// Kernel B: HMMA flash attention, split-bf16, 16-real-key GEMM2, split-K x2.
// grid (32, 16): blockIdx.x = 128-query tile, blockIdx.y = b. 512 threads.
// Warps 0..7: queries (w*16), keys 0..511. Warps 8..15: same queries, keys 512..1023.
// smem: phi_h 16KB | phi_l 16KB | g_h 32x2064B | g_l 32x2064B | part 19KB
// ---------------------------------------------------------------------------
#define PHI_H 0
#define PHI_L 16384
#define G_H   32768
#define G_L   98816
#define GSTRB 2064
#define PART  164864
#define SMEM_ATTN 184320

__global__ __launch_bounds__(512) void attn_mma_kernel()
{
    extern __shared__ char smem[];
    const int tid = threadIdx.x;
    const int lane = tid & 31;
    const int w = tid >> 5;        // 0..15
    const int wq = w & 7;          // query-set id
    const int team = w >> 3;       // 0/1 (key half)
    const int gid = lane >> 2;     // group id 0..7
    const int tig = lane & 3;      // thread in group
    const int b = blockIdx.y;
    const int q0 = blockIdx.x * 128;

    // fill phi planes (contiguous copy)
    {
        const uint4* ph = (const uint4*)(d_phih + (size_t)b * HWP * CK);
        const uint4* pl = (const uint4*)(d_phil + (size_t)b * HWP * CK);
        uint4* sh = (uint4*)(smem + PHI_H);
        uint4* sl = (uint4*)(smem + PHI_L);
        for (int i = tid; i < 1024; i += 512) { sh[i] = ph[i]; sl[i] = pl[i]; }
    }
    // fill g planes (32 rows x 2048B, padded stride 2064B)
    for (int i = tid; i < 4096; i += 512) {
        int c = i >> 7, j = i & 127;
        *(uint4*)(smem + G_H + c * GSTRB + j * 16) =
            *(const uint4*)(d_gh + ((size_t)b * CV + c) * HWP + j * 8);
        *(uint4*)(smem + G_L + c * GSTRB + j * 16) =
            *(const uint4*)(d_gl + ((size_t)b * CV + c) * HWP + j * 8);
    }

    // theta A fragments (constant across key loop)
    const int qb = q0 + wq * 16;
    const float* th = d_theta + (size_t)b * CK * HW;
    float t00 = th[(2 * tig) * HW + qb + gid];
    float t01 = th[(2 * tig + 1) * HW + qb + gid];
    float t10 = th[(2 * tig) * HW + qb + gid + 8];
    float t11 = th[(2 * tig + 1) * HW + qb + gid + 8];
    uint32_t ah0, al0, ah1, al1;
    split2(t00, t01, ah0, al0);
    split2(t10, t11, ah1, al1);
    __syncthreads();

    float o[4][4];
#pragma unroll
    for (int nf = 0; nf < 4; nf++)
#pragma unroll
        for (int j = 0; j < 4; j++) o[nf][j] = 0.f;
    float den0 = 0.f, den1 = 0.f;

    const uint32_t phi_off = gid * 16 + tig * 4;
    const int m_start = team * 512;

#pragma unroll 2
    for (int m0 = m_start; m0 < m_start + 512; m0 += 16) {
        // ---- GEMM1 for 16 keys (two 8-key halves) ----
        uint32_t bh0 = *(uint32_t*)(smem + PHI_H + m0 * 16 + phi_off);
        uint32_t bl0 = *(uint32_t*)(smem + PHI_L + m0 * 16 + phi_off);
        uint32_t bh1 = *(uint32_t*)(smem + PHI_H + (m0 + 8) * 16 + phi_off);
        uint32_t bl1 = *(uint32_t*)(smem + PHI_L + (m0 + 8) * 16 + phi_off);
        float sA0 = 0.f, sA1 = 0.f, sA2 = 0.f, sA3 = 0.f;
        float sB0 = 0.f, sB1 = 0.f, sB2 = 0.f, sB3 = 0.f;
        MMA16816(sA0, sA1, sA2, sA3, ah0, ah1, al0, al1, bh0, bh0);
        MMA16816(sA0, sA1, sA2, sA3, ah0, ah1, al0, al1, bl0, bl0);
        MMA16816(sB0, sB1, sB2, sB3, ah0, ah1, al0, al1, bh1, bh1);
        MMA16816(sB0, sB1, sB2, sB3, ah0, ah1, al0, al1, bl1, bl1);

        // ---- exp + split: build GEMM2 A-fragment [E(k0-7)|E(k8-15)] ----
        float e0 = __expf(sA0), e1 = __expf(sA1), e2 = __expf(sA2), e3 = __expf(sA3);
        float e4 = __expf(sB0), e5 = __expf(sB1), e6 = __expf(sB2), e7 = __expf(sB3);
        den0 += (e0 + e1) + (e4 + e5);
        den1 += (e2 + e3) + (e6 + e7);
        uint32_t Ah0, Al0, Ah1, Al1, Ah2, Al2, Ah3, Al3;
        split2(e0, e1, Ah0, Al0);   // a0: row gid,   cols 2tig,+1  (keys m0+2tig)
        split2(e2, e3, Ah1, Al1);   // a1: row gid+8
        split2(e4, e5, Ah2, Al2);   // a2: row gid,   cols 8+2tig   (keys m0+8+2tig)
        split2(e6, e7, Ah3, Al3);   // a3: row gid+8

        // ---- GEMM2: 3 MMAs per 8-channel block, 16 real keys each ----
        const uint32_t mo0 = (uint32_t)(m0 + 2 * tig) * 2 + gid * GSTRB;
        const uint32_t mo1 = mo0 + 16;
#pragma unroll
        for (int nf = 0; nf < 4; nf++) {
            const char* gh_base = smem + G_H + nf * 8 * GSTRB;
            const char* gl_base = smem + G_L + nf * 8 * GSTRB;
            uint32_t b0h = *(uint32_t*)(gh_base + mo0);
            uint32_t b1h = *(uint32_t*)(gh_base + mo1);
            uint32_t b0l = *(uint32_t*)(gl_base + mo0);
            uint32_t b1l = *(uint32_t*)(gl_base + mo1);
            MMA16816(o[nf][0], o[nf][1], o[nf][2], o[nf][3],
                     Ah0, Ah1, Ah2, Ah3, b0h, b1h);       // Eh * gh
            MMA16816(o[nf][0], o[nf][1], o[nf][2], o[nf][3],
                     Ah0, Ah1, Ah2, Ah3, b0l, b1l);       // Eh * gl
            MMA16816(o[nf][0], o[nf][1], o[nf][2], o[nf][3],
                     Al0, Al1, Al2, Al3, b0h, b1h);       // El * gh
        }
    }

    // ---- split-K combine: team1 -> smem, team0 adds ----
    if (team == 1) {
        float* pp = (float*)(smem + PART) + ((w - 8) * 32 + lane) * 19;
#pragma unroll
        for (int nf = 0; nf < 4; nf++)
#pragma unroll
            for (int j = 0; j < 4; j++) pp[nf * 4 + j] = o[nf][j];
        pp[16] = den0; pp[17] = den1;
    }
    __syncthreads();
    if (team == 0) {
        const float* pp = (const float*)(smem + PART) + (w * 32 + lane) * 19;
#pragma unroll
        for (int nf = 0; nf < 4; nf++)
#pragma unroll
            for (int j = 0; j < 4; j++) o[nf][j] += pp[nf * 4 + j];
        den0 += pp[16]; den1 += pp[17];

        // denominator: reduce over the 4 lanes sharing each query row
        den0 += __shfl_xor_sync(0xffffffffu, den0, 1);
        den0 += __shfl_xor_sync(0xffffffffu, den0, 2);
        den1 += __shfl_xor_sync(0xffffffffu, den1, 1);
        den1 += __shfl_xor_sync(0xffffffffu, den1, 2);
        float i0 = 1.f / den0, i1 = 1.f / den1;

        float* base = d_ot + ((size_t)b * HW + qb + gid) * CV;
#pragma unroll
        for (int nf = 0; nf < 4; nf++) {
            int c = nf * 8 + 2 * tig;
            *(float2*)(base + c)          = make_float2(o[nf][0] * i0, o[nf][1] * i0);
            *(float2*)(base + 8 * CV + c) = make_float2(o[nf][2] * i1, o[nf][3] * i1);
        }
    }
}

// ---------------------------------------------------------------------------
// Kernel C: out = gamma * (w_o @ o) + x.
// ---------------------------------------------------------------------------
__global__ __launch_bounds__(256) void out_kernel(
    const float* __restrict__ x,
    const float* __restrict__ w_o,
    const float* __restrict__ gamma_p,
    float* __restrict__ out)
{
    __shared__ float wo_s[64 * 32];
    __shared__ float o_s[256 * 33];

    int b = blockIdx.y;
    int p0 = blockIdx.x * 256;
    int t = threadIdx.x;
    float gamma = *gamma_p;

    for (int i = t; i < 2048; i += 256) wo_s[i] = w_o[i];
    for (int i = t; i < 8192; i += 256) {
        int pp = i >> 5, c = i & 31;
        o_s[pp * 33 + c] = d_ot[((size_t)b * HW + p0) * CV + i];
    }
    __syncthreads();

    float acc[64];
#pragma unroll
    for (int ch = 0; ch < 64; ch++) acc[ch] = 0.f;
    for (int c = 0; c < 32; c++) {
        float ov = o_s[t * 33 + c];
#pragma unroll
        for (int ch = 0; ch < 64; ch++) acc[ch] += wo_s[ch * 32 + c] * ov;
    }

    int p = p0 + t;
    const float* xb = x + (size_t)b * NC * HW;
    float* ob = out + (size_t)b * NC * HW;
#pragma unroll
    for (int ch = 0; ch < 64; ch++)
        ob[(size_t)ch * HW + p] = gamma * acc[ch] + xb[(size_t)ch * HW + p];
}

// ---------------------------------------------------------------------------
extern "C" void kernel_launch(void* const* d_in, const int* in_sizes, int n_in,
                              void* d_out, int out_size)
{
    const float* x       = (const float*)d_in[0];
    const float* w_theta = (const float*)d_in[1];
    const float* w_phi   = (const float*)d_in[2];
    const float* w_g     = (const float*)d_in[3];
    const float* w_o     = (const float*)d_in[4];
    const float* gamma_p = (const float*)d_in[5];
    float* out = (float*)d_out;

    proj_kernel<<<dim3(16, 2, 16), 128>>>(x, w_theta, w_phi, w_g);

    cudaFuncSetAttribute(attn_mma_kernel, cudaFuncAttributeMaxDynamicSharedMemorySize,
                         SMEM_ATTN);
    attn_mma_kernel<<<dim3(32, 16), 512, SMEM_ATTN>>>();

    out_kernel<<<dim3(16, 16), 256>>>(x, w_o, gamma_p, out);
}

// round 9
// speedup vs baseline: 2.2089x; 1.4526x over previous
#include <cuda_runtime.h>
#include <cuda_bf16.h>
#include <cstdint>

#define NB 16
#define NC 64
#define HW 4096      // 64*64
#define HWP 1024     // 32*32
#define CK 8         // C/8
#define CV 32        // C/2

// Scratch (device globals; no allocation allowed)
__device__ float d_theta[NB * CK * HW];                 // [b][k][n] fp32
__device__ __nv_bfloat16 d_phih[NB * HWP * CK];         // [b][m][k] hi
__device__ __nv_bfloat16 d_phil[NB * HWP * CK];         // [b][m][k] lo
__device__ __nv_bfloat16 d_gh[NB * CV * HWP];           // [b][c][m] hi
__device__ __nv_bfloat16 d_gl[NB * CV * HWP];           // [b][c][m] lo
__device__ float d_ot[NB * HW * CV];                    // [b][n][c]

// ---------------------------------------------------------------------------
__device__ __forceinline__ uint32_t pack2(float a, float b) {
    __nv_bfloat162 t = __floats2bfloat162_rn(a, b);
    return *(uint32_t*)&t;
}
// split (a,b) -> packed hi pair, packed lo (residual) pair
__device__ __forceinline__ void split2(float a, float b, uint32_t& hi, uint32_t& lo) {
    __nv_bfloat16 ha = __float2bfloat16_rn(a), hb = __float2bfloat16_rn(b);
    hi = ((uint32_t)*(unsigned short*)&hb << 16) | (uint32_t)*(unsigned short*)&ha;
    lo = pack2(a - __bfloat162float(ha), b - __bfloat162float(hb));
}
__device__ __forceinline__ void split1(float v, __nv_bfloat16& h, __nv_bfloat16& l) {
    h = __float2bfloat16_rn(v);
    l = __float2bfloat16_rn(v - __bfloat162float(h));
}

#define MMA16816(c0,c1,c2,c3,a0,a1,a2,a3,b0,b1) \
    asm volatile("mma.sync.aligned.m16n8k16.row.col.f32.bf16.bf16.f32 " \
        "{%0,%1,%2,%3}, {%4,%5,%6,%7}, {%8,%9}, {%0,%1,%2,%3};" \
        : "+f"(c0),"+f"(c1),"+f"(c2),"+f"(c3) \
        : "r"(a0),"r"(a1),"r"(a2),"r"(a3),"r"(b0),"r"(b1))

// ---------------------------------------------------------------------------
// Kernel A: 1x1 conv projections + 2x2 maxpool; low-smem two-pass staging.
// grid (32, 2, 16): x = pooled row hc (image rows 2hc,2hc+1), y = channel half,
// z = batch. half 0: theta(8)+phi(8)+g(0..7); half 1: g(8..31).
// smem: w_s 6KB + x_s 16KB = 22KB  -> ~6 CTAs/SM.
// ---------------------------------------------------------------------------
__global__ __launch_bounds__(128) void proj_kernel(
    const float* __restrict__ x,
    const float* __restrict__ w_theta,
    const float* __restrict__ w_phi,
    const float* __restrict__ w_g)
{
    __shared__ float w_s[24 * 64];      // 6KB
    __shared__ float x_s[32 * 128];     // 16KB; reused as pooling staging [128][25]

    const int b = blockIdx.z;
    const int hc = blockIdx.x;
    const int half = blockIdx.y;
    const int t = threadIdx.x;

    for (int i = t; i < 24 * 64; i += 128) {
        int r = half * 24 + (i >> 6), c = i & 63;
        float wv = (r < 8) ? w_theta[r * 64 + c]
                 : (r < 16) ? w_phi[(r - 8) * 64 + c]
                            : w_g[(r - 16) * 64 + c];
        w_s[i] = wv;
    }

    // Rows 2hc,2hc+1 are 128 contiguous floats per channel (W=64).
    const float* xb = x + ((size_t)b * NC) * HW + (size_t)hc * 128;

    float acc[24];
#pragma unroll
    for (int k = 0; k < 24; k++) acc[k] = 0.f;

#pragma unroll 1
    for (int pass = 0; pass < 2; pass++) {
        const float* xp = xb + (size_t)(pass * 32) * HW;
#pragma unroll 8
        for (int c = 0; c < 32; c++) x_s[c * 128 + t] = xp[(size_t)c * HW + t];
        __syncthreads();
        const int cw0 = pass * 32;
        for (int c = 0; c < 32; c++) {
            float xv = x_s[c * 128 + t];
#pragma unroll
            for (int k = 0; k < 24; k++) acc[k] += w_s[k * 64 + cw0 + c] * xv;
        }
        __syncthreads();   // x_s free for next pass / pooling reuse
    }

    if (half == 0) {
        int p = hc * 128 + t;
        float* th = d_theta + (size_t)b * CK * HW;
#pragma unroll
        for (int k = 0; k < 8; k++) th[k * HW + p] = acc[k];
    }

    // stage pooled channels: half0 -> acc[8..23] (16), half1 -> acc[0..23] (24)
    const int nst = half ? 24 : 16;
    const int off = half ? 0 : 8;
    for (int k = 0; k < nst; k++) x_s[t * 25 + k] = acc[off + k];
    __syncthreads();

    if (t < 32) {
        int r0 = 2 * t, r1 = 2 * t + 1, r2 = 64 + 2 * t, r3 = 65 + 2 * t;
        int m = hc * 32 + t;
        for (int k = 0; k < nst; k++) {
            float v = fmaxf(fmaxf(x_s[r0 * 25 + k], x_s[r1 * 25 + k]),
                            fmaxf(x_s[r2 * 25 + k], x_s[r3 * 25 + k]));
            int kk = half ? (24 + k) : (8 + k);   // row in 48-channel space
            __nv_bfloat16 h, l;
            split1(v, h, l);
            if (kk < 16) {                        // phi channel kk-8
                size_t o = ((size_t)b * HWP + m) * CK + (kk - 8);
                d_phih[o] = h; d_phil[o] = l;
            } else {                              // g channel kk-16
                size_t o = ((size_t)b * CV + (kk - 16)) * HWP + m;
                d_gh[o] = h; d_gl[o] = l;
            }
        }
    }
}

// ---------------------------------------------------------------------------
// Kernel B: HMMA flash attention, split-bf16, 16-real-key GEMM2, split-K x2.
// grid (32, 16): blockIdx.x = 128-query tile, blockIdx.y = b. 512 threads.
// Warps 0..7: queries (w*16), keys 0..511. Warps 8..15: same queries, keys 512..1023.
// smem: phi_h 16KB | phi_l 16KB | g_h 32x2064B | g_l 32x2064B | part 19KB
// ---------------------------------------------------------------------------
#define PHI_H 0
#define PHI_L 16384
#define G_H   32768
#define G_L   98816
#define GSTRB 2064
#define PART  164864
#define SMEM_ATTN 184320

__global__ __launch_bounds__(512) void attn_mma_kernel()
{
    extern __shared__ char smem[];
    const int tid = threadIdx.x;
    const int lane = tid & 31;
    const int w = tid >> 5;        // 0..15
    const int wq = w & 7;          // query-set id
    const int team = w >> 3;       // 0/1 (key half)
    const int gid = lane >> 2;     // group id 0..7
    const int tig = lane & 3;      // thread in group
    const int b = blockIdx.y;
    const int q0 = blockIdx.x * 128;

    // fill phi planes (contiguous copy)
    {
        const uint4* ph = (const uint4*)(d_phih + (size_t)b * HWP * CK);
        const uint4* pl = (const uint4*)(d_phil + (size_t)b * HWP * CK);
        uint4* sh = (uint4*)(smem + PHI_H);
        uint4* sl = (uint4*)(smem + PHI_L);
        for (int i = tid; i < 1024; i += 512) { sh[i] = ph[i]; sl[i] = pl[i]; }
    }
    // fill g planes (32 rows x 2048B, padded stride 2064B)
    for (int i = tid; i < 4096; i += 512) {
        int c = i >> 7, j = i & 127;
        *(uint4*)(smem + G_H + c * GSTRB + j * 16) =
            *(const uint4*)(d_gh + ((size_t)b * CV + c) * HWP + j * 8);
        *(uint4*)(smem + G_L + c * GSTRB + j * 16) =
            *(const uint4*)(d_gl + ((size_t)b * CV + c) * HWP + j * 8);
    }

    // theta A fragments (constant across key loop)
    const int qb = q0 + wq * 16;
    const float* th = d_theta + (size_t)b * CK * HW;
    float t00 = th[(2 * tig) * HW + qb + gid];
    float t01 = th[(2 * tig + 1) * HW + qb + gid];
    float t10 = th[(2 * tig) * HW + qb + gid + 8];
    float t11 = th[(2 * tig + 1) * HW + qb + gid + 8];
    uint32_t ah0, al0, ah1, al1;
    split2(t00, t01, ah0, al0);
    split2(t10, t11, ah1, al1);
    __syncthreads();

    float o[4][4];
#pragma unroll
    for (int nf = 0; nf < 4; nf++)
#pragma unroll
        for (int j = 0; j < 4; j++) o[nf][j] = 0.f;
    float den0 = 0.f, den1 = 0.f;

    const uint32_t phi_off = gid * 16 + tig * 4;
    const int m_start = team * 512;

#pragma unroll 2
    for (int m0 = m_start; m0 < m_start + 512; m0 += 16) {
        // ---- GEMM1 for 16 keys (two 8-key halves) ----
        uint32_t bh0 = *(uint32_t*)(smem + PHI_H + m0 * 16 + phi_off);
        uint32_t bl0 = *(uint32_t*)(smem + PHI_L + m0 * 16 + phi_off);
        uint32_t bh1 = *(uint32_t*)(smem + PHI_H + (m0 + 8) * 16 + phi_off);
        uint32_t bl1 = *(uint32_t*)(smem + PHI_L + (m0 + 8) * 16 + phi_off);
        float sA0 = 0.f, sA1 = 0.f, sA2 = 0.f, sA3 = 0.f;
        float sB0 = 0.f, sB1 = 0.f, sB2 = 0.f, sB3 = 0.f;
        MMA16816(sA0, sA1, sA2, sA3, ah0, ah1, al0, al1, bh0, bh0);
        MMA16816(sA0, sA1, sA2, sA3, ah0, ah1, al0, al1, bl0, bl0);
        MMA16816(sB0, sB1, sB2, sB3, ah0, ah1, al0, al1, bh1, bh1);
        MMA16816(sB0, sB1, sB2, sB3, ah0, ah1, al0, al1, bl1, bl1);

        // ---- exp + split: build GEMM2 A-fragment [E(k0-7)|E(k8-15)] ----
        float e0 = __expf(sA0), e1 = __expf(sA1), e2 = __expf(sA2), e3 = __expf(sA3);
        float e4 = __expf(sB0), e5 = __expf(sB1), e6 = __expf(sB2), e7 = __expf(sB3);
        den0 += (e0 + e1) + (e4 + e5);
        den1 += (e2 + e3) + (e6 + e7);
        uint32_t Ah0, Al0, Ah1, Al1, Ah2, Al2, Ah3, Al3;
        split2(e0, e1, Ah0, Al0);   // a0: row gid,   cols 2tig,+1  (keys m0+2tig)
        split2(e2, e3, Ah1, Al1);   // a1: row gid+8
        split2(e4, e5, Ah2, Al2);   // a2: row gid,   cols 8+2tig   (keys m0+8+2tig)
        split2(e6, e7, Ah3, Al3);   // a3: row gid+8

        // ---- GEMM2: 3 MMAs per 8-channel block, 16 real keys each ----
        const uint32_t mo0 = (uint32_t)(m0 + 2 * tig) * 2 + gid * GSTRB;
        const uint32_t mo1 = mo0 + 16;
#pragma unroll
        for (int nf = 0; nf < 4; nf++) {
            const char* gh_base = smem + G_H + nf * 8 * GSTRB;
            const char* gl_base = smem + G_L + nf * 8 * GSTRB;
            uint32_t b0h = *(uint32_t*)(gh_base + mo0);
            uint32_t b1h = *(uint32_t*)(gh_base + mo1);
            uint32_t b0l = *(uint32_t*)(gl_base + mo0);
            uint32_t b1l = *(uint32_t*)(gl_base + mo1);
            MMA16816(o[nf][0], o[nf][1], o[nf][2], o[nf][3],
                     Ah0, Ah1, Ah2, Ah3, b0h, b1h);       // Eh * gh
            MMA16816(o[nf][0], o[nf][1], o[nf][2], o[nf][3],
                     Ah0, Ah1, Ah2, Ah3, b0l, b1l);       // Eh * gl
            MMA16816(o[nf][0], o[nf][1], o[nf][2], o[nf][3],
                     Al0, Al1, Al2, Al3, b0h, b1h);       // El * gh
        }
    }

    // ---- split-K combine: team1 -> smem, team0 adds ----
    if (team == 1) {
        float* pp = (float*)(smem + PART) + ((w - 8) * 32 + lane) * 19;
#pragma unroll
        for (int nf = 0; nf < 4; nf++)
#pragma unroll
            for (int j = 0; j < 4; j++) pp[nf * 4 + j] = o[nf][j];
        pp[16] = den0; pp[17] = den1;
    }
    __syncthreads();
    if (team == 0) {
        const float* pp = (const float*)(smem + PART) + (w * 32 + lane) * 19;
#pragma unroll
        for (int nf = 0; nf < 4; nf++)
#pragma unroll
            for (int j = 0; j < 4; j++) o[nf][j] += pp[nf * 4 + j];
        den0 += pp[16]; den1 += pp[17];

        // denominator: reduce over the 4 lanes sharing each query row
        den0 += __shfl_xor_sync(0xffffffffu, den0, 1);
        den0 += __shfl_xor_sync(0xffffffffu, den0, 2);
        den1 += __shfl_xor_sync(0xffffffffu, den1, 1);
        den1 += __shfl_xor_sync(0xffffffffu, den1, 2);
        float i0 = 1.f / den0, i1 = 1.f / den1;

        float* base = d_ot + ((size_t)b * HW + qb + gid) * CV;
#pragma unroll
        for (int nf = 0; nf < 4; nf++) {
            int c = nf * 8 + 2 * tig;
            *(float2*)(base + c)          = make_float2(o[nf][0] * i0, o[nf][1] * i0);
            *(float2*)(base + 8 * CV + c) = make_float2(o[nf][2] * i1, o[nf][3] * i1);
        }
    }
}

// ---------------------------------------------------------------------------
// Kernel C: out = gamma * (w_o @ o) + x.
// ---------------------------------------------------------------------------
__global__ __launch_bounds__(256) void out_kernel(
    const float* __restrict__ x,
    const float* __restrict__ w_o,
    const float* __restrict__ gamma_p,
    float* __restrict__ out)
{
    __shared__ float wo_s[64 * 32];
    __shared__ float o_s[256 * 33];

    int b = blockIdx.y;
    int p0 = blockIdx.x * 256;
    int t = threadIdx.x;
    float gamma = *gamma_p;

    for (int i = t; i < 2048; i += 256) wo_s[i] = w_o[i];
    for (int i = t; i < 8192; i += 256) {
        int pp = i >> 5, c = i & 31;
        o_s[pp * 33 + c] = d_ot[((size_t)b * HW + p0) * CV + i];
    }
    __syncthreads();

    float acc[64];
#pragma unroll
    for (int ch = 0; ch < 64; ch++) acc[ch] = 0.f;
    for (int c = 0; c < 32; c++) {
        float ov = o_s[t * 33 + c];
#pragma unroll
        for (int ch = 0; ch < 64; ch++) acc[ch] += wo_s[ch * 32 + c] * ov;
    }

    int p = p0 + t;
    const float* xb = x + (size_t)b * NC * HW;
    float* ob = out + (size_t)b * NC * HW;
#pragma unroll
    for (int ch = 0; ch < 64; ch++)
        ob[(size_t)ch * HW + p] = gamma * acc[ch] + xb[(size_t)ch * HW + p];
}

// ---------------------------------------------------------------------------
extern "C" void kernel_launch(void* const* d_in, const int* in_sizes, int n_in,
                              void* d_out, int out_size)
{
    const float* x       = (const float*)d_in[0];
    const float* w_theta = (const float*)d_in[1];
    const float* w_phi   = (const float*)d_in[2];
    const float* w_g     = (const float*)d_in[3];
    const float* w_o     = (const float*)d_in[4];
    const float* gamma_p = (const float*)d_in[5];
    float* out = (float*)d_out;

    proj_kernel<<<dim3(32, 2, 16), 128>>>(x, w_theta, w_phi, w_g);

    cudaFuncSetAttribute(attn_mma_kernel, cudaFuncAttributeMaxDynamicSharedMemorySize,
                         SMEM_ATTN);
    attn_mma_kernel<<<dim3(32, 16), 512, SMEM_ATTN>>>();

    out_kernel<<<dim3(16, 16), 256>>>(x, w_o, gamma_p, out);
}

// round 11
// speedup vs baseline: 2.6317x; 1.1914x over previous
#include <cuda_runtime.h>
#include <cuda_fp16.h>
#include <cstdint>

#define NB 16
#define NC 64
#define HW 4096      // 64*64
#define HWP 1024     // 32*32
#define CK 8         // C/8
#define CV 32        // C/2

// Scratch (device globals; no allocation allowed)
__device__ float d_theta[NB * CK * HW];          // [b][k][n] fp32
__device__ __half d_phih[NB * HWP * CK];         // [b][m][k] hi
__device__ __half d_phil[NB * HWP * CK];         // [b][m][k] lo
__device__ __half d_gh[NB * CV * HWP];           // [b][c][m] fp16
__device__ float d_ot[NB * HW * CV];             // [b][n][c]

// ---------------------------------------------------------------------------
__device__ __forceinline__ uint32_t pack2h(float a, float b) {
    __half2 t = __floats2half2_rn(a, b);
    return *(uint32_t*)&t;
}
// split (a,b) -> packed fp16 hi pair, packed fp16 lo (residual) pair
__device__ __forceinline__ void split2h(float a, float b, uint32_t& hi, uint32_t& lo) {
    __half ha = __float2half_rn(a), hb = __float2half_rn(b);
    hi = ((uint32_t)*(unsigned short*)&hb << 16) | (uint32_t)*(unsigned short*)&ha;
    lo = pack2h(a - __half2float(ha), b - __half2float(hb));
}
__device__ __forceinline__ void split1h(float v, __half& h, __half& l) {
    h = __float2half_rn(v);
    l = __float2half_rn(v - __half2float(h));
}

#define MMAH16816(c0,c1,c2,c3,a0,a1,a2,a3,b0,b1) \
    asm volatile("mma.sync.aligned.m16n8k16.row.col.f32.f16.f16.f32 " \
        "{%0,%1,%2,%3}, {%4,%5,%6,%7}, {%8,%9}, {%0,%1,%2,%3};" \
        : "+f"(c0),"+f"(c1),"+f"(c2),"+f"(c3) \
        : "r"(a0),"r"(a1),"r"(a2),"r"(a3),"r"(b0),"r"(b1))

// ---------------------------------------------------------------------------
// Kernel A: 1x1 conv projections + 2x2 maxpool; two-pass staging,
// w_s TRANSPOSED [c][k] so the inner loop reads weights as 6x LDS.128.
// grid (32, 2, 16): x = pooled row hc, y = channel half, z = batch.
// half 0: theta(8)+phi(8)+g(0..7); half 1: g(8..31).
// ---------------------------------------------------------------------------
__global__ __launch_bounds__(128) void proj_kernel(
    const float* __restrict__ x,
    const float* __restrict__ w_theta,
    const float* __restrict__ w_phi,
    const float* __restrict__ w_g)
{
    __shared__ float w_s[64 * 24];      // [c][k], 6KB
    __shared__ float x_s[32 * 128];     // 16KB; reused as pooling staging [128][25]

    const int b = blockIdx.z;
    const int hc = blockIdx.x;
    const int half = blockIdx.y;
    const int t = threadIdx.x;

    for (int i = t; i < 24 * 64; i += 128) {
        int k = i >> 6, c = i & 63;          // local k 0..23, input channel c
        int r = half * 24 + k;               // global output-channel row
        float wv = (r < 8) ? w_theta[r * 64 + c]
                 : (r < 16) ? w_phi[(r - 8) * 64 + c]
                            : w_g[(r - 16) * 64 + c];
        w_s[c * 24 + k] = wv;                // transposed store
    }

    // Rows 2hc,2hc+1 are 128 contiguous floats per channel (W=64).
    const float* xb = x + ((size_t)b * NC) * HW + (size_t)hc * 128;

    float acc[24];
#pragma unroll
    for (int k = 0; k < 24; k++) acc[k] = 0.f;

#pragma unroll 1
    for (int pass = 0; pass < 2; pass++) {
        const float* xp = xb + (size_t)(pass * 32) * HW;
#pragma unroll 8
        for (int c = 0; c < 32; c++) x_s[c * 128 + t] = xp[(size_t)c * HW + t];
        __syncthreads();
        const int cw0 = pass * 32;
        for (int c = 0; c < 32; c++) {
            float xv = x_s[c * 128 + t];
            const float4* wr = (const float4*)&w_s[(cw0 + c) * 24];
            float wv[24];
#pragma unroll
            for (int j = 0; j < 6; j++) {
                float4 wq = wr[j];
                wv[4 * j] = wq.x; wv[4 * j + 1] = wq.y;
                wv[4 * j + 2] = wq.z; wv[4 * j + 3] = wq.w;
            }
#pragma unroll
            for (int k = 0; k < 24; k++) acc[k] += wv[k] * xv;
        }
        __syncthreads();   // x_s free for next pass / pooling reuse
    }

    if (half == 0) {
        int p = hc * 128 + t;
        float* th = d_theta + (size_t)b * CK * HW;
#pragma unroll
        for (int k = 0; k < 8; k++) th[k * HW + p] = acc[k];
    }

    // stage pooled channels: half0 -> acc[8..23] (16), half1 -> acc[0..23] (24)
    const int nst = half ? 24 : 16;
    const int off = half ? 0 : 8;
    for (int k = 0; k < nst; k++) x_s[t * 25 + k] = acc[off + k];
    __syncthreads();

    if (t < 32) {
        int r0 = 2 * t, r1 = 2 * t + 1, r2 = 64 + 2 * t, r3 = 65 + 2 * t;
        int m = hc * 32 + t;
        for (int k = 0; k < nst; k++) {
            float v = fmaxf(fmaxf(x_s[r0 * 25 + k], x_s[r1 * 25 + k]),
                            fmaxf(x_s[r2 * 25 + k], x_s[r3 * 25 + k]));
            int kk = half ? (24 + k) : (8 + k);   // row in 48-channel space
            if (kk < 16) {                        // phi channel kk-8
                __half h, l;
                split1h(v, h, l);
                size_t o = ((size_t)b * HWP + m) * CK + (kk - 8);
                d_phih[o] = h; d_phil[o] = l;
            } else {                              // g channel kk-16 (fp16 single)
                size_t o = ((size_t)b * CV + (kk - 16)) * HWP + m;
                d_gh[o] = __float2half_rn(v);
            }
        }
    }
}

// ---------------------------------------------------------------------------
// Kernel B: fp16 HMMA flash attention with ONLINE row max, split-K x2,
// 12 MMAs / 16 keys. grid (32, 16). 512 threads.
// E = exp(s - rowmax) in (0,1]: no overflow, no clamp, fp16-safe.
// smem: phi_h 16KB | phi_l 16KB | g 32x2064B (66KB); PART overlays phi.
// Total 96.5KB -> 2 CTAs/SM.
// ---------------------------------------------------------------------------
#define PHI_H 0
#define PHI_L 16384
#define G_H   32768
#define GSTRB 2064
#define PART  0          /* overlays phi planes after main loop */
#define SMEM_ATTN 98816

__global__ __launch_bounds__(512, 2) void attn_mma_kernel()
{
    extern __shared__ char smem[];
    const int tid = threadIdx.x;
    const int lane = tid & 31;
    const int w = tid >> 5;        // 0..15
    const int wq = w & 7;          // query-set id
    const int team = w >> 3;       // 0/1 (key half)
    const int gid = lane >> 2;     // group id 0..7
    const int tig = lane & 3;      // thread in group
    const int b = blockIdx.y;
    const int q0 = blockIdx.x * 128;

    // fill phi planes (contiguous copy)
    {
        const uint4* ph = (const uint4*)(d_phih + (size_t)b * HWP * CK);
        const uint4* pl = (const uint4*)(d_phil + (size_t)b * HWP * CK);
        uint4* sh = (uint4*)(smem + PHI_H);
        uint4* sl = (uint4*)(smem + PHI_L);
        for (int i = tid; i < 1024; i += 512) { sh[i] = ph[i]; sl[i] = pl[i]; }
    }
    // fill g plane (32 rows x 2048B, padded stride 2064B)
    for (int i = tid; i < 4096; i += 512) {
        int c = i >> 7, j = i & 127;
        *(uint4*)(smem + G_H + c * GSTRB + j * 16) =
            *(const uint4*)(d_gh + ((size_t)b * CV + c) * HWP + j * 8);
    }

    // theta A fragments (constant across key loop)
    const int qb = q0 + wq * 16;
    const float* th = d_theta + (size_t)b * CK * HW;
    float t00 = th[(2 * tig) * HW + qb + gid];
    float t01 = th[(2 * tig + 1) * HW + qb + gid];
    float t10 = th[(2 * tig) * HW + qb + gid + 8];
    float t11 = th[(2 * tig + 1) * HW + qb + gid + 8];
    uint32_t ah0, al0, ah1, al1;
    split2h(t00, t01, ah0, al0);
    split2h(t10, t11, ah1, al1);
    __syncthreads();

    float o[4][4];
#pragma unroll
    for (int nf = 0; nf < 4; nf++)
#pragma unroll
        for (int j = 0; j < 4; j++) o[nf][j] = 0.f;
    float den0 = 0.f, den1 = 0.f;
    float mx0 = -1e30f, mx1 = -1e30f;     // running row maxes

    const uint32_t phi_off = gid * 16 + tig * 4;
    const int m_start = team * 512;

#pragma unroll 2
    for (int m0 = m_start; m0 < m_start + 512; m0 += 16) {
        // ---- GEMM1 for 16 keys (two 8-key halves); exact 4-product split ----
        uint32_t bh0 = *(uint32_t*)(smem + PHI_H + m0 * 16 + phi_off);
        uint32_t bl0 = *(uint32_t*)(smem + PHI_L + m0 * 16 + phi_off);
        uint32_t bh1 = *(uint32_t*)(smem + PHI_H + (m0 + 8) * 16 + phi_off);
        uint32_t bl1 = *(uint32_t*)(smem + PHI_L + (m0 + 8) * 16 + phi_off);
        float sA0 = 0.f, sA1 = 0.f, sA2 = 0.f, sA3 = 0.f;
        float sB0 = 0.f, sB1 = 0.f, sB2 = 0.f, sB3 = 0.f;
        MMAH16816(sA0, sA1, sA2, sA3, ah0, ah1, al0, al1, bh0, bh0);
        MMAH16816(sA0, sA1, sA2, sA3, ah0, ah1, al0, al1, bl0, bl0);
        MMAH16816(sB0, sB1, sB2, sB3, ah0, ah1, al0, al1, bh1, bh1);
        MMAH16816(sB0, sB1, sB2, sB3, ah0, ah1, al0, al1, bl1, bl1);

        // ---- online row max (row gid: sA0,sA1,sB0,sB1; row gid+8: sA2,sA3,sB2,sB3)
        float c0 = fmaxf(fmaxf(sA0, sA1), fmaxf(sB0, sB1));
        float c1 = fmaxf(fmaxf(sA2, sA3), fmaxf(sB2, sB3));
        c0 = fmaxf(c0, __shfl_xor_sync(0xffffffffu, c0, 1));
        c0 = fmaxf(c0, __shfl_xor_sync(0xffffffffu, c0, 2));
        c1 = fmaxf(c1, __shfl_xor_sync(0xffffffffu, c1, 1));
        c1 = fmaxf(c1, __shfl_xor_sync(0xffffffffu, c1, 2));
        float nm0 = fmaxf(mx0, c0), nm1 = fmaxf(mx1, c1);
        float sc0 = __expf(mx0 - nm0), sc1 = __expf(mx1 - nm1);
        mx0 = nm0; mx1 = nm1;
        den0 *= sc0; den1 *= sc1;
#pragma unroll
        for (int nf = 0; nf < 4; nf++) {
            o[nf][0] *= sc0; o[nf][1] *= sc0;
            o[nf][2] *= sc1; o[nf][3] *= sc1;
        }

        // ---- exp relative to row max: E in (0,1] ----
        float e0 = __expf(sA0 - nm0), e1 = __expf(sA1 - nm0);
        float e2 = __expf(sA2 - nm1), e3 = __expf(sA3 - nm1);
        float e4 = __expf(sB0 - nm0), e5 = __expf(sB1 - nm0);
        float e6 = __expf(sB2 - nm1), e7 = __expf(sB3 - nm1);
        den0 += (e0 + e1) + (e4 + e5);
        den1 += (e2 + e3) + (e6 + e7);
        uint32_t Ah0, Al0, Ah1, Al1, Ah2, Al2, Ah3, Al3;
        split2h(e0, e1, Ah0, Al0);   // a0: row gid,   keys m0+2tig,+1
        split2h(e2, e3, Ah1, Al1);   // a1: row gid+8
        split2h(e4, e5, Ah2, Al2);   // a2: row gid,   keys m0+8+2tig,+1
        split2h(e6, e7, Ah3, Al3);   // a3: row gid+8

        // ---- GEMM2: 2 MMAs per 8-channel block (Eh*g + El*g), 16 real keys ----
        const uint32_t mo0 = (uint32_t)(m0 + 2 * tig) * 2 + gid * GSTRB;
        const uint32_t mo1 = mo0 + 16;
#pragma unroll
        for (int nf = 0; nf < 4; nf++) {
            const char* g_base = smem + G_H + nf * 8 * GSTRB;
            uint32_t b0 = *(uint32_t*)(g_base + mo0);
            uint32_t b1 = *(uint32_t*)(g_base + mo1);
            MMAH16816(o[nf][0], o[nf][1], o[nf][2], o[nf][3],
                      Ah0, Ah1, Ah2, Ah3, b0, b1);        // Eh * g
            MMAH16816(o[nf][0], o[nf][1], o[nf][2], o[nf][3],
                      Al0, Al1, Al2, Al3, b0, b1);        // El * g
        }
    }

    __syncthreads();   // phi planes dead; PART overlays them

    // ---- split-K combine with max reconciliation ----
    if (team == 1) {
        float* pp = (float*)(smem + PART) + ((w - 8) * 32 + lane) * 20;
#pragma unroll
        for (int nf = 0; nf < 4; nf++)
#pragma unroll
            for (int j = 0; j < 4; j++) pp[nf * 4 + j] = o[nf][j];
        pp[16] = den0; pp[17] = den1;
        pp[18] = mx0;  pp[19] = mx1;
    }
    __syncthreads();
    if (team == 0) {
        const float* pp = (const float*)(smem + PART) + (w * 32 + lane) * 20;
        float om0 = pp[18], om1 = pp[19];
        float gm0 = fmaxf(mx0, om0), gm1 = fmaxf(mx1, om1);
        float a0 = __expf(mx0 - gm0), b0s = __expf(om0 - gm0);
        float a1 = __expf(mx1 - gm1), b1s = __expf(om1 - gm1);
#pragma unroll
        for (int nf = 0; nf < 4; nf++) {
            o[nf][0] = o[nf][0] * a0 + pp[nf * 4 + 0] * b0s;
            o[nf][1] = o[nf][1] * a0 + pp[nf * 4 + 1] * b0s;
            o[nf][2] = o[nf][2] * a1 + pp[nf * 4 + 2] * b1s;
            o[nf][3] = o[nf][3] * a1 + pp[nf * 4 + 3] * b1s;
        }
        den0 = den0 * a0 + pp[16] * b0s;
        den1 = den1 * a1 + pp[17] * b1s;

        // denominator: reduce over the 4 lanes sharing each query row
        den0 += __shfl_xor_sync(0xffffffffu, den0, 1);
        den0 += __shfl_xor_sync(0xffffffffu, den0, 2);
        den1 += __shfl_xor_sync(0xffffffffu, den1, 1);
        den1 += __shfl_xor_sync(0xffffffffu, den1, 2);
        float i0 = 1.f / den0, i1 = 1.f / den1;

        float* base = d_ot + ((size_t)b * HW + qb + gid) * CV;
#pragma unroll
        for (int nf = 0; nf < 4; nf++) {
            int c = nf * 8 + 2 * tig;
            *(float2*)(base + c)          = make_float2(o[nf][0] * i0, o[nf][1] * i0);
            *(float2*)(base + 8 * CV + c) = make_float2(o[nf][2] * i1, o[nf][3] * i1);
        }
    }
}

// ---------------------------------------------------------------------------
// Kernel C: out = gamma * (w_o @ o) + x.
// ---------------------------------------------------------------------------
__global__ __launch_bounds__(256) void out_kernel(
    const float* __restrict__ x,
    const float* __restrict__ w_o,
    const float* __restrict__ gamma_p,
    float* __restrict__ out)
{
    __shared__ float wo_s[64 * 32];
    __shared__ float o_s[256 * 33];

    int b = blockIdx.y;
    int p0 = blockIdx.x * 256;
    int t = threadIdx.x;
    float gamma = *gamma_p;

    for (int i = t; i < 2048; i += 256) wo_s[i] = w_o[i];
    for (int i = t; i < 8192; i += 256) {
        int pp = i >> 5, c = i & 31;
        o_s[pp * 33 + c] = d_ot[((size_t)b * HW + p0) * CV + i];
    }
    __syncthreads();

    float acc[64];
#pragma unroll
    for (int ch = 0; ch < 64; ch++) acc[ch] = 0.f;
    for (int c = 0; c < 32; c++) {
        float ov = o_s[t * 33 + c];
#pragma unroll
        for (int ch = 0; ch < 64; ch++) acc[ch] += wo_s[ch * 32 + c] * ov;
    }

    int p = p0 + t;
    const float* xb = x + (size_t)b * NC * HW;
    float* ob = out + (size_t)b * NC * HW;
#pragma unroll
    for (int ch = 0; ch < 64; ch++)
        ob[(size_t)ch * HW + p] = gamma * acc[ch] + xb[(size_t)ch * HW + p];
}

// ---------------------------------------------------------------------------
extern "C" void kernel_launch(void* const* d_in, const int* in_sizes, int n_in,
                              void* d_out, int out_size)
{
    const float* x       = (const float*)d_in[0];
    const float* w_theta = (const float*)d_in[1];
    const float* w_phi   = (const float*)d_in[2];
    const float* w_g     = (const float*)d_in[3];
    const float* w_o     = (const float*)d_in[4];
    const float* gamma_p = (const float*)d_in[5];
    float* out = (float*)d_out;

    proj_kernel<<<dim3(32, 2, 16), 128>>>(x, w_theta, w_phi, w_g);

    cudaFuncSetAttribute(attn_mma_kernel, cudaFuncAttributeMaxDynamicSharedMemorySize,
                         SMEM_ATTN);
    attn_mma_kernel<<<dim3(32, 16), 512, SMEM_ATTN>>>();

    out_kernel<<<dim3(16, 16), 256>>>(x, w_o, gamma_p, out);
}

// round 12
// speedup vs baseline: 3.0278x; 1.1505x over previous
#include <cuda_runtime.h>
#include <cuda_fp16.h>
#include <cstdint>

#define NB 16
#define NC 64
#define HW 4096      // 64*64
#define HWP 1024     // 32*32
#define CK 8         // C/8
#define CV 32        // C/2

// Scratch (device globals; no allocation allowed)
__device__ float d_theta[NB * CK * HW];          // [b][k][n] fp32
__device__ __half d_phih[NB * HWP * CK];         // [b][m][k] hi
__device__ __half d_phil[NB * HWP * CK];         // [b][m][k] lo
__device__ __half d_gh[NB * CV * HWP];           // [b][c][m] fp16
__device__ float d_ot[NB * HW * CV];             // [b][n][c]

// ---------------------------------------------------------------------------
__device__ __forceinline__ uint32_t pack2h(float a, float b) {
    __half2 t = __floats2half2_rn(a, b);
    return *(uint32_t*)&t;
}
// split (a,b) -> packed fp16 hi pair, packed fp16 lo (residual) pair
__device__ __forceinline__ void split2h(float a, float b, uint32_t& hi, uint32_t& lo) {
    __half ha = __float2half_rn(a), hb = __float2half_rn(b);
    hi = ((uint32_t)*(unsigned short*)&hb << 16) | (uint32_t)*(unsigned short*)&ha;
    lo = pack2h(a - __half2float(ha), b - __half2float(hb));
}
__device__ __forceinline__ void split1h(float v, __half& h, __half& l) {
    h = __float2half_rn(v);
    l = __float2half_rn(v - __half2float(h));
}

#define MMAH16816(c0,c1,c2,c3,a0,a1,a2,a3,b0,b1) \
    asm volatile("mma.sync.aligned.m16n8k16.row.col.f32.f16.f16.f32 " \
        "{%0,%1,%2,%3}, {%4,%5,%6,%7}, {%8,%9}, {%0,%1,%2,%3};" \
        : "+f"(c0),"+f"(c1),"+f"(c2),"+f"(c3) \
        : "r"(a0),"r"(a1),"r"(a2),"r"(a3),"r"(b0),"r"(b1))

// ---------------------------------------------------------------------------
// Kernel A: 1x1 conv projections + 2x2 maxpool. MERGED halves: one 256-thread
// CTA computes all 48 output channels for a 128-pixel tile; x staged ONCE.
// grid (32, 16): x = pooled row hc (image rows 2hc,2hc+1), y = batch.
// thread t: pixel p = t&127, channel-half h = t>>7 (24 channels each).
// dyn smem: w_s [64][48] 12KB | x_s [32][128] 16KB | pool [128][49] 25.1KB
// -> 53.4KB, 4 CTAs/SM, whole grid resident in one wave.
// ---------------------------------------------------------------------------
#define PJ_W    0
#define PJ_X    (48 * 64 * 4)
#define PJ_POOL (PJ_X + 32 * 128 * 4)
#define SMEM_PROJ (PJ_POOL + 128 * 49 * 4)

__global__ __launch_bounds__(256) void proj_kernel(
    const float* __restrict__ x,
    const float* __restrict__ w_theta,
    const float* __restrict__ w_phi,
    const float* __restrict__ w_g)
{
    extern __shared__ char psm[];
    float* w_s  = (float*)(psm + PJ_W);      // [c][r] transposed
    float* x_s  = (float*)(psm + PJ_X);
    float* pool = (float*)(psm + PJ_POOL);   // [pixel][48ch] stride 49

    const int b = blockIdx.y;
    const int hc = blockIdx.x;
    const int t = threadIdx.x;
    const int p = t & 127;
    const int h = t >> 7;

    for (int i = t; i < 48 * 64; i += 256) {
        int r = i >> 6, c = i & 63;
        float wv = (r < 8) ? w_theta[r * 64 + c]
                 : (r < 16) ? w_phi[(r - 8) * 64 + c]
                            : w_g[(r - 16) * 64 + c];
        w_s[c * 48 + r] = wv;
    }

    // Rows 2hc,2hc+1 are 128 contiguous floats per channel (W=64).
    const float* xb = x + ((size_t)b * NC) * HW + (size_t)hc * 128;

    float acc[24];
#pragma unroll
    for (int k = 0; k < 24; k++) acc[k] = 0.f;

#pragma unroll 1
    for (int pass = 0; pass < 2; pass++) {
        const float* xp = xb + (size_t)(pass * 32) * HW;
#pragma unroll 4
        for (int i = t; i < 4096; i += 256)
            x_s[i] = xp[(size_t)(i >> 7) * HW + (i & 127)];
        __syncthreads();
        const int cw0 = pass * 32;
        for (int c = 0; c < 32; c++) {
            float xv = x_s[c * 128 + p];
            const float4* wr = (const float4*)&w_s[(cw0 + c) * 48 + h * 24];
            float wv[24];
#pragma unroll
            for (int j = 0; j < 6; j++) {
                float4 wq = wr[j];
                wv[4 * j] = wq.x; wv[4 * j + 1] = wq.y;
                wv[4 * j + 2] = wq.z; wv[4 * j + 3] = wq.w;
            }
#pragma unroll
            for (int k = 0; k < 24; k++) acc[k] += wv[k] * xv;
        }
        __syncthreads();
    }

    if (h == 0) {
        int pp = hc * 128 + p;
        float* th = d_theta + (size_t)b * CK * HW;
#pragma unroll
        for (int k = 0; k < 8; k++) th[k * HW + pp] = acc[k];
    }

    // stage all 48 channels for pooling: col = h*24 + k
#pragma unroll
    for (int k = 0; k < 24; k++) pool[p * 49 + h * 24 + k] = acc[k];
    __syncthreads();

    if (t < 128) {
        int wc = t & 31, cg = t >> 5;           // 32 pooled cols x 4 channel groups
        int r0 = 2 * wc, r1 = 2 * wc + 1, r2 = 64 + 2 * wc, r3 = 65 + 2 * wc;
        int m = hc * 32 + wc;
#pragma unroll
        for (int j = 0; j < 10; j++) {
            int c48 = 8 + cg * 10 + j;          // pooled channels live in cols 8..47
            float v = fmaxf(fmaxf(pool[r0 * 49 + c48], pool[r1 * 49 + c48]),
                            fmaxf(pool[r2 * 49 + c48], pool[r3 * 49 + c48]));
            if (c48 < 16) {                     // phi channel c48-8
                __half hh, ll;
                split1h(v, hh, ll);
                size_t o = ((size_t)b * HWP + m) * CK + (c48 - 8);
                d_phih[o] = hh; d_phil[o] = ll;
            } else {                            // g channel c48-16 (fp16 single)
                size_t o = ((size_t)b * CV + (c48 - 16)) * HWP + m;
                d_gh[o] = __float2half_rn(v);
            }
        }
    }
}

// ---------------------------------------------------------------------------
// Kernel B: fp16 HMMA flash attention, online row max (conditional rescale),
// single-fp16 E in GEMM2: 8 MMAs / 16 keys. Split-K x2. grid (32,16), 512 thr.
// smem: phi_h 16KB | phi_l 16KB | g 32x2064B (66KB); PART overlays phi.
// Total 96.5KB -> 2 CTAs/SM.
// ---------------------------------------------------------------------------
#define PHI_H 0
#define PHI_L 16384
#define G_H   32768
#define GSTRB 2064
#define PART  0          /* overlays phi planes after main loop */
#define SMEM_ATTN 98816

__global__ __launch_bounds__(512, 2) void attn_mma_kernel()
{
    extern __shared__ char smem[];
    const int tid = threadIdx.x;
    const int lane = tid & 31;
    const int w = tid >> 5;        // 0..15
    const int wq = w & 7;          // query-set id
    const int team = w >> 3;       // 0/1 (key half)
    const int gid = lane >> 2;     // group id 0..7
    const int tig = lane & 3;      // thread in group
    const int b = blockIdx.y;
    const int q0 = blockIdx.x * 128;

    // fill phi planes (contiguous copy)
    {
        const uint4* ph = (const uint4*)(d_phih + (size_t)b * HWP * CK);
        const uint4* pl = (const uint4*)(d_phil + (size_t)b * HWP * CK);
        uint4* sh = (uint4*)(smem + PHI_H);
        uint4* sl = (uint4*)(smem + PHI_L);
        for (int i = tid; i < 1024; i += 512) { sh[i] = ph[i]; sl[i] = pl[i]; }
    }
    // fill g plane (32 rows x 2048B, padded stride 2064B)
    for (int i = tid; i < 4096; i += 512) {
        int c = i >> 7, j = i & 127;
        *(uint4*)(smem + G_H + c * GSTRB + j * 16) =
            *(const uint4*)(d_gh + ((size_t)b * CV + c) * HWP + j * 8);
    }

    // theta A fragments (constant across key loop)
    const int qb = q0 + wq * 16;
    const float* th = d_theta + (size_t)b * CK * HW;
    float t00 = th[(2 * tig) * HW + qb + gid];
    float t01 = th[(2 * tig + 1) * HW + qb + gid];
    float t10 = th[(2 * tig) * HW + qb + gid + 8];
    float t11 = th[(2 * tig + 1) * HW + qb + gid + 8];
    uint32_t ah0, al0, ah1, al1;
    split2h(t00, t01, ah0, al0);
    split2h(t10, t11, ah1, al1);
    __syncthreads();

    float o[4][4];
#pragma unroll
    for (int nf = 0; nf < 4; nf++)
#pragma unroll
        for (int j = 0; j < 4; j++) o[nf][j] = 0.f;
    float den0 = 0.f, den1 = 0.f;
    float mx0 = -1e30f, mx1 = -1e30f;     // running row maxes

    const uint32_t phi_off = gid * 16 + tig * 4;
    const int m_start = team * 512;

#pragma unroll 2
    for (int m0 = m_start; m0 < m_start + 512; m0 += 16) {
        // ---- GEMM1 for 16 keys (two 8-key halves); exact 4-product split ----
        uint32_t bh0 = *(uint32_t*)(smem + PHI_H + m0 * 16 + phi_off);
        uint32_t bl0 = *(uint32_t*)(smem + PHI_L + m0 * 16 + phi_off);
        uint32_t bh1 = *(uint32_t*)(smem + PHI_H + (m0 + 8) * 16 + phi_off);
        uint32_t bl1 = *(uint32_t*)(smem + PHI_L + (m0 + 8) * 16 + phi_off);
        float sA0 = 0.f, sA1 = 0.f, sA2 = 0.f, sA3 = 0.f;
        float sB0 = 0.f, sB1 = 0.f, sB2 = 0.f, sB3 = 0.f;
        MMAH16816(sA0, sA1, sA2, sA3, ah0, ah1, al0, al1, bh0, bh0);
        MMAH16816(sA0, sA1, sA2, sA3, ah0, ah1, al0, al1, bl0, bl0);
        MMAH16816(sB0, sB1, sB2, sB3, ah0, ah1, al0, al1, bh1, bh1);
        MMAH16816(sB0, sB1, sB2, sB3, ah0, ah1, al0, al1, bl1, bl1);

        // ---- chunk row max (row gid: sA0,sA1,sB0,sB1; row gid+8: sA2,sA3,sB2,sB3)
        float c0 = fmaxf(fmaxf(sA0, sA1), fmaxf(sB0, sB1));
        float c1 = fmaxf(fmaxf(sA2, sA3), fmaxf(sB2, sB3));
        c0 = fmaxf(c0, __shfl_xor_sync(0xffffffffu, c0, 1));
        c0 = fmaxf(c0, __shfl_xor_sync(0xffffffffu, c0, 2));
        c1 = fmaxf(c1, __shfl_xor_sync(0xffffffffu, c1, 1));
        c1 = fmaxf(c1, __shfl_xor_sync(0xffffffffu, c1, 2));

        // ---- conditional rescale: only when some row's max grew (warp-uniform)
        if (__any_sync(0xffffffffu, (c0 > mx0) | (c1 > mx1))) {
            float nm0 = fmaxf(mx0, c0), nm1 = fmaxf(mx1, c1);
            float sc0 = __expf(mx0 - nm0), sc1 = __expf(mx1 - nm1);
            mx0 = nm0; mx1 = nm1;
            den0 *= sc0; den1 *= sc1;
#pragma unroll
            for (int nf = 0; nf < 4; nf++) {
                o[nf][0] *= sc0; o[nf][1] *= sc0;
                o[nf][2] *= sc1; o[nf][3] *= sc1;
            }
        }

        // ---- exp relative to row max: E in (0,1], single fp16 ----
        float e0 = __expf(sA0 - mx0), e1 = __expf(sA1 - mx0);
        float e2 = __expf(sA2 - mx1), e3 = __expf(sA3 - mx1);
        float e4 = __expf(sB0 - mx0), e5 = __expf(sB1 - mx0);
        float e6 = __expf(sB2 - mx1), e7 = __expf(sB3 - mx1);
        den0 += (e0 + e1) + (e4 + e5);
        den1 += (e2 + e3) + (e6 + e7);
        uint32_t Ah0 = pack2h(e0, e1);   // a0: row gid,   keys m0+2tig,+1
        uint32_t Ah1 = pack2h(e2, e3);   // a1: row gid+8
        uint32_t Ah2 = pack2h(e4, e5);   // a2: row gid,   keys m0+8+2tig,+1
        uint32_t Ah3 = pack2h(e6, e7);   // a3: row gid+8

        // ---- GEMM2: 1 MMA per 8-channel block (E*g), 16 real keys ----
        const uint32_t mo0 = (uint32_t)(m0 + 2 * tig) * 2 + gid * GSTRB;
        const uint32_t mo1 = mo0 + 16;
#pragma unroll
        for (int nf = 0; nf < 4; nf++) {
            const char* g_base = smem + G_H + nf * 8 * GSTRB;
            uint32_t b0 = *(uint32_t*)(g_base + mo0);
            uint32_t b1 = *(uint32_t*)(g_base + mo1);
            MMAH16816(o[nf][0], o[nf][1], o[nf][2], o[nf][3],
                      Ah0, Ah1, Ah2, Ah3, b0, b1);
        }
    }

    __syncthreads();   // phi planes dead; PART overlays them

    // ---- split-K combine with max reconciliation ----
    if (team == 1) {
        float* pp = (float*)(smem + PART) + ((w - 8) * 32 + lane) * 20;
#pragma unroll
        for (int nf = 0; nf < 4; nf++)
#pragma unroll
            for (int j = 0; j < 4; j++) pp[nf * 4 + j] = o[nf][j];
        pp[16] = den0; pp[17] = den1;
        pp[18] = mx0;  pp[19] = mx1;
    }
    __syncthreads();
    if (team == 0) {
        const float* pp = (const float*)(smem + PART) + (w * 32 + lane) * 20;
        float om0 = pp[18], om1 = pp[19];
        float gm0 = fmaxf(mx0, om0), gm1 = fmaxf(mx1, om1);
        float a0 = __expf(mx0 - gm0), b0s = __expf(om0 - gm0);
        float a1 = __expf(mx1 - gm1), b1s = __expf(om1 - gm1);
#pragma unroll
        for (int nf = 0; nf < 4; nf++) {
            o[nf][0] = o[nf][0] * a0 + pp[nf * 4 + 0] * b0s;
            o[nf][1] = o[nf][1] * a0 + pp[nf * 4 + 1] * b0s;
            o[nf][2] = o[nf][2] * a1 + pp[nf * 4 + 2] * b1s;
            o[nf][3] = o[nf][3] * a1 + pp[nf * 4 + 3] * b1s;
        }
        den0 = den0 * a0 + pp[16] * b0s;
        den1 = den1 * a1 + pp[17] * b1s;

        // denominator: reduce over the 4 lanes sharing each query row
        den0 += __shfl_xor_sync(0xffffffffu, den0, 1);
        den0 += __shfl_xor_sync(0xffffffffu, den0, 2);
        den1 += __shfl_xor_sync(0xffffffffu, den1, 1);
        den1 += __shfl_xor_sync(0xffffffffu, den1, 2);
        float i0 = 1.f / den0, i1 = 1.f / den1;

        float* base = d_ot + ((size_t)b * HW + qb + gid) * CV;
#pragma unroll
        for (int nf = 0; nf < 4; nf++) {
            int c = nf * 8 + 2 * tig;
            *(float2*)(base + c)          = make_float2(o[nf][0] * i0, o[nf][1] * i0);
            *(float2*)(base + 8 * CV + c) = make_float2(o[nf][2] * i1, o[nf][3] * i1);
        }
    }
}

// ---------------------------------------------------------------------------
// Kernel C: out = gamma * (w_o @ o) + x.
// ---------------------------------------------------------------------------
__global__ __launch_bounds__(256) void out_kernel(
    const float* __restrict__ x,
    const float* __restrict__ w_o,
    const float* __restrict__ gamma_p,
    float* __restrict__ out)
{
    __shared__ float wo_s[64 * 32];
    __shared__ float o_s[256 * 33];

    int b = blockIdx.y;
    int p0 = blockIdx.x * 256;
    int t = threadIdx.x;
    float gamma = *gamma_p;

    for (int i = t; i < 2048; i += 256) wo_s[i] = w_o[i];
    for (int i = t; i < 8192; i += 256) {
        int pp = i >> 5, c = i & 31;
        o_s[pp * 33 + c] = d_ot[((size_t)b * HW + p0) * CV + i];
    }
    __syncthreads();

    float acc[64];
#pragma unroll
    for (int ch = 0; ch < 64; ch++) acc[ch] = 0.f;
    for (int c = 0; c < 32; c++) {
        float ov = o_s[t * 33 + c];
#pragma unroll
        for (int ch = 0; ch < 64; ch++) acc[ch] += wo_s[ch * 32 + c] * ov;
    }

    int p = p0 + t;
    const float* xb = x + (size_t)b * NC * HW;
    float* ob = out + (size_t)b * NC * HW;
#pragma unroll
    for (int ch = 0; ch < 64; ch++)
        ob[(size_t)ch * HW + p] = gamma * acc[ch] + xb[(size_t)ch * HW + p];
}

// ---------------------------------------------------------------------------
extern "C" void kernel_launch(void* const* d_in, const int* in_sizes, int n_in,
                              void* d_out, int out_size)
{
    const float* x       = (const float*)d_in[0];
    const float* w_theta = (const float*)d_in[1];
    const float* w_phi   = (const float*)d_in[2];
    const float* w_g     = (const float*)d_in[3];
    const float* w_o     = (const float*)d_in[4];
    const float* gamma_p = (const float*)d_in[5];
    float* out = (float*)d_out;

    cudaFuncSetAttribute(proj_kernel, cudaFuncAttributeMaxDynamicSharedMemorySize,
                         SMEM_PROJ);
    proj_kernel<<<dim3(32, 16), 256, SMEM_PROJ>>>(x, w_theta, w_phi, w_g);

    cudaFuncSetAttribute(attn_mma_kernel, cudaFuncAttributeMaxDynamicSharedMemorySize,
                         SMEM_ATTN);
    attn_mma_kernel<<<dim3(32, 16), 512, SMEM_ATTN>>>();

    out_kernel<<<dim3(16, 16), 256>>>(x, w_o, gamma_p, out);
}

// round 13
// speedup vs baseline: 3.4239x; 1.1308x over previous
#include <cuda_runtime.h>
#include <cuda_fp16.h>
#include <cstdint>

#define NB 16
#define NC 64
#define HW 4096      // 64*64
#define HWP 1024     // 32*32
#define CK 8         // C/8
#define CV 32        // C/2

// Scratch (device globals; no allocation allowed)
__device__ float d_theta[NB * CK * HW];          // [b][k][n] fp32
__device__ __half d_phih[NB * HWP * CK];         // [b][m][k] hi
__device__ __half d_phil[NB * HWP * CK];         // [b][m][k] lo
__device__ __half d_gh[NB * CV * HWP];           // [b][c][m] fp16

// ---------------------------------------------------------------------------
__device__ __forceinline__ uint32_t pack2h(float a, float b) {
    __half2 t = __floats2half2_rn(a, b);
    return *(uint32_t*)&t;
}
// split (a,b) -> packed fp16 hi pair, packed fp16 lo (residual) pair
__device__ __forceinline__ void split2h(float a, float b, uint32_t& hi, uint32_t& lo) {
    __half ha = __float2half_rn(a), hb = __float2half_rn(b);
    hi = ((uint32_t)*(unsigned short*)&hb << 16) | (uint32_t)*(unsigned short*)&ha;
    lo = pack2h(a - __half2float(ha), b - __half2float(hb));
}
__device__ __forceinline__ void split1h(float v, __half& h, __half& l) {
    h = __float2half_rn(v);
    l = __float2half_rn(v - __half2float(h));
}

#define MMAH16816(c0,c1,c2,c3,a0,a1,a2,a3,b0,b1) \
    asm volatile("mma.sync.aligned.m16n8k16.row.col.f32.f16.f16.f32 " \
        "{%0,%1,%2,%3}, {%4,%5,%6,%7}, {%8,%9}, {%0,%1,%2,%3};" \
        : "+f"(c0),"+f"(c1),"+f"(c2),"+f"(c3) \
        : "r"(a0),"r"(a1),"r"(a2),"r"(a3),"r"(b0),"r"(b1))

// ---------------------------------------------------------------------------
// Kernel A: 1x1 conv projections + 2x2 maxpool. 2 pixels/thread, 48 channels
// per CTA over a 256-pixel tile (4 image rows). x staged once per pass.
// grid (16, 16): x = tile hc (image rows 4hc..4hc+3), y = batch.
// thread t: pixel pair pp = t&127 (pixels 2pp,2pp+1), half h = t>>7 (24 ch).
// dyn smem: w_s [64][48] 12KB | x_s [32][256] 32KB overlaid by pool [256][49]
// -> 62.5KB, 3 CTAs/SM, single wave.
// ---------------------------------------------------------------------------
#define PJ_W    0
#define PJ_X    (48 * 64 * 4)
#define SMEM_PROJ (PJ_X + 256 * 49 * 4)

__global__ __launch_bounds__(256) void proj_kernel(
    const float* __restrict__ x,
    const float* __restrict__ w_theta,
    const float* __restrict__ w_phi,
    const float* __restrict__ w_g)
{
    extern __shared__ char psm[];
    float* w_s  = (float*)(psm + PJ_W);      // [c][r] transposed
    float* x_s  = (float*)(psm + PJ_X);      // [32][256]
    float* pool = (float*)(psm + PJ_X);      // [256 px][48 ch] stride 49 (overlay)

    const int b = blockIdx.y;
    const int hc = blockIdx.x;
    const int t = threadIdx.x;
    const int pp = t & 127;
    const int h = t >> 7;

    for (int i = t; i < 48 * 64; i += 256) {
        int r = i >> 6, c = i & 63;
        float wv = (r < 8) ? w_theta[r * 64 + c]
                 : (r < 16) ? w_phi[(r - 8) * 64 + c]
                            : w_g[(r - 16) * 64 + c];
        w_s[c * 48 + r] = wv;
    }

    // Rows 4hc..4hc+3 are 256 contiguous floats per channel (W=64).
    const float* xb = x + ((size_t)b * NC) * HW + (size_t)hc * 256;

    float acc0[24], acc1[24];
#pragma unroll
    for (int k = 0; k < 24; k++) { acc0[k] = 0.f; acc1[k] = 0.f; }

#pragma unroll 1
    for (int pass = 0; pass < 2; pass++) {
        const float* xp = xb + (size_t)(pass * 32) * HW;
#pragma unroll 4
        for (int i = t; i < 8192; i += 256)
            x_s[i] = xp[(size_t)(i >> 8) * HW + (i & 255)];
        __syncthreads();
        const int cw0 = pass * 32;
        for (int c = 0; c < 32; c++) {
            float2 xv = *(float2*)&x_s[c * 256 + 2 * pp];
            const float4* wr = (const float4*)&w_s[(cw0 + c) * 48 + h * 24];
            float wv[24];
#pragma unroll
            for (int j = 0; j < 6; j++) {
                float4 wq = wr[j];
                wv[4 * j] = wq.x; wv[4 * j + 1] = wq.y;
                wv[4 * j + 2] = wq.z; wv[4 * j + 3] = wq.w;
            }
#pragma unroll
            for (int k = 0; k < 24; k++) {
                acc0[k] += wv[k] * xv.x;
                acc1[k] += wv[k] * xv.y;
            }
        }
        __syncthreads();   // x_s free for next pass / pooling overlay
    }

    if (h == 0) {
        int p = hc * 256 + 2 * pp;
        float* th = d_theta + (size_t)b * CK * HW;
#pragma unroll
        for (int k = 0; k < 8; k++)
            *(float2*)&th[k * HW + p] = make_float2(acc0[k], acc1[k]);
    }

    // stage all 48 channels for pooling: col = h*24 + k
#pragma unroll
    for (int k = 0; k < 24; k++) {
        pool[(2 * pp) * 49 + h * 24 + k]     = acc0[k];
        pool[(2 * pp + 1) * 49 + h * 24 + k] = acc1[k];
    }
    __syncthreads();

    {
        int mp = t & 63, cg = t >> 6;           // 64 pooled px x 4 channel groups
        int pr = mp >> 5, wc = mp & 31;         // pooled row (0/1), pooled col
        int p00 = pr * 128 + 2 * wc;            // local pixel indices
        int p01 = p00 + 1, p10 = p00 + 64, p11 = p00 + 65;
        int m = (hc * 2 + pr) * 32 + wc;        // global pooled index
#pragma unroll
        for (int j = 0; j < 10; j++) {
            int c48 = 8 + cg * 10 + j;          // pooled channels live in cols 8..47
            float v = fmaxf(fmaxf(pool[p00 * 49 + c48], pool[p01 * 49 + c48]),
                            fmaxf(pool[p10 * 49 + c48], pool[p11 * 49 + c48]));
            if (c48 < 16) {                     // phi channel c48-8
                __half hh, ll;
                split1h(v, hh, ll);
                size_t o = ((size_t)b * HWP + m) * CK + (c48 - 8);
                d_phih[o] = hh; d_phil[o] = ll;
            } else {                            // g channel c48-16 (fp16 single)
                size_t o = ((size_t)b * CV + (c48 - 16)) * HWP + m;
                d_gh[o] = __float2half_rn(v);
            }
        }
    }
}

// ---------------------------------------------------------------------------
// Kernel B: fp16 HMMA flash attention + FUSED output projection/residual.
// Online row max (conditional rescale), single-fp16 E, 8 MMAs / 16 keys,
// split-K x2. grid (32,16), 512 threads.
// After attention, o[128q][32c] lives in-CTA -> apply w_o, gamma, +x, write out.
// smem: phi_h 16KB | phi_l 16KB | g 66KB. Epilogue overlays: PART on phi,
// o_s (17.4KB) + w_s (8KB) on g. Total 96.5KB -> 2 CTAs/SM.
// ---------------------------------------------------------------------------
#define PHI_H 0
#define PHI_L 16384
#define G_H   32768
#define GSTRB 2064
#define PART  0                      /* overlays phi planes after main loop */
#define OS    32768                  /* o_s [128][34] floats, overlays g */
#define WS    (32768 + 128 * 34 * 4) /* w_s [32][64] floats */
#define SMEM_ATTN 98816

__global__ __launch_bounds__(512, 2) void attn_mma_kernel(
    const float* __restrict__ x,
    const float* __restrict__ w_o,
    const float* __restrict__ gamma_p,
    float* __restrict__ out)
{
    extern __shared__ char smem[];
    const int tid = threadIdx.x;
    const int lane = tid & 31;
    const int w = tid >> 5;        // 0..15
    const int wq = w & 7;          // query-set id
    const int team = w >> 3;       // 0/1 (key half)
    const int gid = lane >> 2;     // group id 0..7
    const int tig = lane & 3;      // thread in group
    const int b = blockIdx.y;
    const int q0 = blockIdx.x * 128;

    // fill phi planes (contiguous copy)
    {
        const uint4* ph = (const uint4*)(d_phih + (size_t)b * HWP * CK);
        const uint4* pl = (const uint4*)(d_phil + (size_t)b * HWP * CK);
        uint4* sh = (uint4*)(smem + PHI_H);
        uint4* sl = (uint4*)(smem + PHI_L);
        for (int i = tid; i < 1024; i += 512) { sh[i] = ph[i]; sl[i] = pl[i]; }
    }
    // fill g plane (32 rows x 2048B, padded stride 2064B)
    for (int i = tid; i < 4096; i += 512) {
        int c = i >> 7, j = i & 127;
        *(uint4*)(smem + G_H + c * GSTRB + j * 16) =
            *(const uint4*)(d_gh + ((size_t)b * CV + c) * HWP + j * 8);
    }

    // theta A fragments (constant across key loop)
    const int qb = q0 + wq * 16;
    const float* th = d_theta + (size_t)b * CK * HW;
    float t00 = th[(2 * tig) * HW + qb + gid];
    float t01 = th[(2 * tig + 1) * HW + qb + gid];
    float t10 = th[(2 * tig) * HW + qb + gid + 8];
    float t11 = th[(2 * tig + 1) * HW + qb + gid + 8];
    uint32_t ah0, al0, ah1, al1;
    split2h(t00, t01, ah0, al0);
    split2h(t10, t11, ah1, al1);
    __syncthreads();

    float o[4][4];
#pragma unroll
    for (int nf = 0; nf < 4; nf++)
#pragma unroll
        for (int j = 0; j < 4; j++) o[nf][j] = 0.f;
    float den0 = 0.f, den1 = 0.f;
    float mx0 = -1e30f, mx1 = -1e30f;     // running row maxes

    const uint32_t phi_off = gid * 16 + tig * 4;
    const int m_start = team * 512;

#pragma unroll 2
    for (int m0 = m_start; m0 < m_start + 512; m0 += 16) {
        // ---- GEMM1 for 16 keys (two 8-key halves); exact 4-product split ----
        uint32_t bh0 = *(uint32_t*)(smem + PHI_H + m0 * 16 + phi_off);
        uint32_t bl0 = *(uint32_t*)(smem + PHI_L + m0 * 16 + phi_off);
        uint32_t bh1 = *(uint32_t*)(smem + PHI_H + (m0 + 8) * 16 + phi_off);
        uint32_t bl1 = *(uint32_t*)(smem + PHI_L + (m0 + 8) * 16 + phi_off);
        float sA0 = 0.f, sA1 = 0.f, sA2 = 0.f, sA3 = 0.f;
        float sB0 = 0.f, sB1 = 0.f, sB2 = 0.f, sB3 = 0.f;
        MMAH16816(sA0, sA1, sA2, sA3, ah0, ah1, al0, al1, bh0, bh0);
        MMAH16816(sA0, sA1, sA2, sA3, ah0, ah1, al0, al1, bl0, bl0);
        MMAH16816(sB0, sB1, sB2, sB3, ah0, ah1, al0, al1, bh1, bh1);
        MMAH16816(sB0, sB1, sB2, sB3, ah0, ah1, al0, al1, bl1, bl1);

        // ---- chunk row max (row gid: sA0,sA1,sB0,sB1; row gid+8: sA2,sA3,sB2,sB3)
        float c0 = fmaxf(fmaxf(sA0, sA1), fmaxf(sB0, sB1));
        float c1 = fmaxf(fmaxf(sA2, sA3), fmaxf(sB2, sB3));
        c0 = fmaxf(c0, __shfl_xor_sync(0xffffffffu, c0, 1));
        c0 = fmaxf(c0, __shfl_xor_sync(0xffffffffu, c0, 2));
        c1 = fmaxf(c1, __shfl_xor_sync(0xffffffffu, c1, 1));
        c1 = fmaxf(c1, __shfl_xor_sync(0xffffffffu, c1, 2));

        // ---- conditional rescale: only when some row's max grew (warp-uniform)
        if (__any_sync(0xffffffffu, (c0 > mx0) | (c1 > mx1))) {
            float nm0 = fmaxf(mx0, c0), nm1 = fmaxf(mx1, c1);
            float sc0 = __expf(mx0 - nm0), sc1 = __expf(mx1 - nm1);
            mx0 = nm0; mx1 = nm1;
            den0 *= sc0; den1 *= sc1;
#pragma unroll
            for (int nf = 0; nf < 4; nf++) {
                o[nf][0] *= sc0; o[nf][1] *= sc0;
                o[nf][2] *= sc1; o[nf][3] *= sc1;
            }
        }

        // ---- exp relative to row max: E in (0,1], single fp16 ----
        float e0 = __expf(sA0 - mx0), e1 = __expf(sA1 - mx0);
        float e2 = __expf(sA2 - mx1), e3 = __expf(sA3 - mx1);
        float e4 = __expf(sB0 - mx0), e5 = __expf(sB1 - mx0);
        float e6 = __expf(sB2 - mx1), e7 = __expf(sB3 - mx1);
        den0 += (e0 + e1) + (e4 + e5);
        den1 += (e2 + e3) + (e6 + e7);
        uint32_t Ah0 = pack2h(e0, e1);   // a0: row gid,   keys m0+2tig,+1
        uint32_t Ah1 = pack2h(e2, e3);   // a1: row gid+8
        uint32_t Ah2 = pack2h(e4, e5);   // a2: row gid,   keys m0+8+2tig,+1
        uint32_t Ah3 = pack2h(e6, e7);   // a3: row gid+8

        // ---- GEMM2: 1 MMA per 8-channel block (E*g), 16 real keys ----
        const uint32_t mo0 = (uint32_t)(m0 + 2 * tig) * 2 + gid * GSTRB;
        const uint32_t mo1 = mo0 + 16;
#pragma unroll
        for (int nf = 0; nf < 4; nf++) {
            const char* g_base = smem + G_H + nf * 8 * GSTRB;
            uint32_t b0 = *(uint32_t*)(g_base + mo0);
            uint32_t b1 = *(uint32_t*)(g_base + mo1);
            MMAH16816(o[nf][0], o[nf][1], o[nf][2], o[nf][3],
                      Ah0, Ah1, Ah2, Ah3, b0, b1);
        }
    }

    __syncthreads();   // phi + g planes dead; overlays become live

    // stage w_o transposed: w_s[c][ch] = w_o[ch][c]
    {
        float* w_s = (float*)(smem + WS);
        for (int i = tid; i < 2048; i += 512) {
            int ch = i >> 5, c = i & 31;
            w_s[c * 64 + ch] = w_o[i];
        }
    }

    // ---- split-K combine with max reconciliation ----
    if (team == 1) {
        float* pp = (float*)(smem + PART) + ((w - 8) * 32 + lane) * 20;
#pragma unroll
        for (int nf = 0; nf < 4; nf++)
#pragma unroll
            for (int j = 0; j < 4; j++) pp[nf * 4 + j] = o[nf][j];
        pp[16] = den0; pp[17] = den1;
        pp[18] = mx0;  pp[19] = mx1;
    }
    __syncthreads();
    if (team == 0) {
        const float* pp = (const float*)(smem + PART) + (w * 32 + lane) * 20;
        float om0 = pp[18], om1 = pp[19];
        float gm0 = fmaxf(mx0, om0), gm1 = fmaxf(mx1, om1);
        float a0 = __expf(mx0 - gm0), b0s = __expf(om0 - gm0);
        float a1 = __expf(mx1 - gm1), b1s = __expf(om1 - gm1);
#pragma unroll
        for (int nf = 0; nf < 4; nf++) {
            o[nf][0] = o[nf][0] * a0 + pp[nf * 4 + 0] * b0s;
            o[nf][1] = o[nf][1] * a0 + pp[nf * 4 + 1] * b0s;
            o[nf][2] = o[nf][2] * a1 + pp[nf * 4 + 2] * b1s;
            o[nf][3] = o[nf][3] * a1 + pp[nf * 4 + 3] * b1s;
        }
        den0 = den0 * a0 + pp[16] * b0s;
        den1 = den1 * a1 + pp[17] * b1s;

        // denominator: reduce over the 4 lanes sharing each query row
        den0 += __shfl_xor_sync(0xffffffffu, den0, 1);
        den0 += __shfl_xor_sync(0xffffffffu, den0, 2);
        den1 += __shfl_xor_sync(0xffffffffu, den1, 1);
        den1 += __shfl_xor_sync(0xffffffffu, den1, 2);
        float i0 = 1.f / den0, i1 = 1.f / den1;

        // write normalized o to smem [q_local][c], stride 34 (float2-aligned)
        float* os = (float*)(smem + OS);
        int ql = wq * 16 + gid;
#pragma unroll
        for (int nf = 0; nf < 4; nf++) {
            int c = nf * 8 + 2 * tig;
            *(float2*)&os[ql * 34 + c]       = make_float2(o[nf][0] * i0, o[nf][1] * i0);
            *(float2*)&os[(ql + 8) * 34 + c] = make_float2(o[nf][2] * i1, o[nf][3] * i1);
        }
    }
    __syncthreads();

    // ---- fused output projection: out = gamma * (w_o @ o) + x ----
    {
        const float* os = (const float*)(smem + OS);
        const float* w_s = (const float*)(smem + WS);
        const float gamma = *gamma_p;
        int q = tid & 127, cg = tid >> 7;       // 128 queries x 4 ch-groups of 16
        float accf[16];
#pragma unroll
        for (int j = 0; j < 16; j++) accf[j] = 0.f;
        for (int c = 0; c < 32; c++) {
            float ov = os[q * 34 + c];
            const float4* wr = (const float4*)&w_s[c * 64 + cg * 16];
#pragma unroll
            for (int j4 = 0; j4 < 4; j4++) {
                float4 wq4 = wr[j4];
                accf[4 * j4]     += wq4.x * ov;
                accf[4 * j4 + 1] += wq4.y * ov;
                accf[4 * j4 + 2] += wq4.z * ov;
                accf[4 * j4 + 3] += wq4.w * ov;
            }
        }
        int p = q0 + q;
        const float* xb = x + (size_t)b * NC * HW + p;
        float* ob = out + (size_t)b * NC * HW + p;
#pragma unroll
        for (int j = 0; j < 16; j++) {
            int ch = cg * 16 + j;
            ob[(size_t)ch * HW] = gamma * accf[j] + xb[(size_t)ch * HW];
        }
    }
}

// ---------------------------------------------------------------------------
extern "C" void kernel_launch(void* const* d_in, const int* in_sizes, int n_in,
                              void* d_out, int out_size)
{
    const float* x       = (const float*)d_in[0];
    const float* w_theta = (const float*)d_in[1];
    const float* w_phi   = (const float*)d_in[2];
    const float* w_g     = (const float*)d_in[3];
    const float* w_o     = (const float*)d_in[4];
    const float* gamma_p = (const float*)d_in[5];
    float* out = (float*)d_out;

    cudaFuncSetAttribute(proj_kernel, cudaFuncAttributeMaxDynamicSharedMemorySize,
                         SMEM_PROJ);
    proj_kernel<<<dim3(16, 16), 256, SMEM_PROJ>>>(x, w_theta, w_phi, w_g);

    cudaFuncSetAttribute(attn_mma_kernel, cudaFuncAttributeMaxDynamicSharedMemorySize,
                         SMEM_ATTN);
    attn_mma_kernel<<<dim3(32, 16), 512, SMEM_ATTN>>>(x, w_o, gamma_p, out);
}

// round 14
// speedup vs baseline: 3.7051x; 1.0821x over previous
#include <cuda_runtime.h>
#include <cuda_fp16.h>
#include <cstdint>

#define NB 16
#define NC 64
#define HW 4096      // 64*64
#define HWP 1024     // 32*32
#define CK 8         // C/8
#define CV 32        // C/2

// Scratch (device globals; no allocation allowed)
__device__ float d_theta[NB * CK * HW];          // [b][k][n] fp32
__device__ __half d_phih[NB * HWP * CK];         // [b][m][k] hi
__device__ __half d_phil[NB * HWP * CK];         // [b][m][k] lo
__device__ __half d_gh[NB * CV * HWP];           // [b][c][m] fp16

// ---------------------------------------------------------------------------
__device__ __forceinline__ uint32_t pack2h(float a, float b) {
    __half2 t = __floats2half2_rn(a, b);
    return *(uint32_t*)&t;
}
// split (a,b) -> packed fp16 hi pair, packed fp16 lo (residual) pair
__device__ __forceinline__ void split2h(float a, float b, uint32_t& hi, uint32_t& lo) {
    __half ha = __float2half_rn(a), hb = __float2half_rn(b);
    hi = ((uint32_t)*(unsigned short*)&hb << 16) | (uint32_t)*(unsigned short*)&ha;
    lo = pack2h(a - __half2float(ha), b - __half2float(hb));
}
__device__ __forceinline__ void split1h(float v, __half& h, __half& l) {
    h = __float2half_rn(v);
    l = __float2half_rn(v - __half2float(h));
}
// packed fp16x2 2^x (one MUFU for two exps; output = ready A-fragment)
__device__ __forceinline__ uint32_t ex2h2(uint32_t s) {
    uint32_t r;
    asm("ex2.approx.f16x2 %0, %1;" : "=r"(r) : "r"(s));
    return r;
}

#define MMAH16816(c0,c1,c2,c3,a0,a1,a2,a3,b0,b1) \
    asm volatile("mma.sync.aligned.m16n8k16.row.col.f32.f16.f16.f32 " \
        "{%0,%1,%2,%3}, {%4,%5,%6,%7}, {%8,%9}, {%0,%1,%2,%3};" \
        : "+f"(c0),"+f"(c1),"+f"(c2),"+f"(c3) \
        : "r"(a0),"r"(a1),"r"(a2),"r"(a3),"r"(b0),"r"(b1))

// ---------------------------------------------------------------------------
// Kernel A: 1x1 conv projections + 2x2 maxpool. 2 pixels/thread, 48 channels
// per CTA over a 256-pixel tile (4 image rows). x staged once per pass.
// grid (16, 16). dyn smem 62.5KB, 3 CTAs/SM, single wave.
// ---------------------------------------------------------------------------
#define PJ_W    0
#define PJ_X    (48 * 64 * 4)
#define SMEM_PROJ (PJ_X + 256 * 49 * 4)

__global__ __launch_bounds__(256) void proj_kernel(
    const float* __restrict__ x,
    const float* __restrict__ w_theta,
    const float* __restrict__ w_phi,
    const float* __restrict__ w_g)
{
    extern __shared__ char psm[];
    float* w_s  = (float*)(psm + PJ_W);      // [c][r] transposed
    float* x_s  = (float*)(psm + PJ_X);      // [32][256]
    float* pool = (float*)(psm + PJ_X);      // [256 px][48 ch] stride 49 (overlay)

    const int b = blockIdx.y;
    const int hc = blockIdx.x;
    const int t = threadIdx.x;
    const int pp = t & 127;
    const int h = t >> 7;

    for (int i = t; i < 48 * 64; i += 256) {
        int r = i >> 6, c = i & 63;
        float wv = (r < 8) ? w_theta[r * 64 + c]
                 : (r < 16) ? w_phi[(r - 8) * 64 + c]
                            : w_g[(r - 16) * 64 + c];
        w_s[c * 48 + r] = wv;
    }

    // Rows 4hc..4hc+3 are 256 contiguous floats per channel (W=64).
    const float* xb = x + ((size_t)b * NC) * HW + (size_t)hc * 256;

    float acc0[24], acc1[24];
#pragma unroll
    for (int k = 0; k < 24; k++) { acc0[k] = 0.f; acc1[k] = 0.f; }

#pragma unroll 1
    for (int pass = 0; pass < 2; pass++) {
        const float* xp = xb + (size_t)(pass * 32) * HW;
#pragma unroll 4
        for (int i = t; i < 8192; i += 256)
            x_s[i] = xp[(size_t)(i >> 8) * HW + (i & 255)];
        __syncthreads();
        const int cw0 = pass * 32;
        for (int c = 0; c < 32; c++) {
            float2 xv = *(float2*)&x_s[c * 256 + 2 * pp];
            const float4* wr = (const float4*)&w_s[(cw0 + c) * 48 + h * 24];
            float wv[24];
#pragma unroll
            for (int j = 0; j < 6; j++) {
                float4 wq = wr[j];
                wv[4 * j] = wq.x; wv[4 * j + 1] = wq.y;
                wv[4 * j + 2] = wq.z; wv[4 * j + 3] = wq.w;
            }
#pragma unroll
            for (int k = 0; k < 24; k++) {
                acc0[k] += wv[k] * xv.x;
                acc1[k] += wv[k] * xv.y;
            }
        }
        __syncthreads();   // x_s free for next pass / pooling overlay
    }

    if (h == 0) {
        int p = hc * 256 + 2 * pp;
        float* th = d_theta + (size_t)b * CK * HW;
#pragma unroll
        for (int k = 0; k < 8; k++)
            *(float2*)&th[k * HW + p] = make_float2(acc0[k], acc1[k]);
    }

    // stage all 48 channels for pooling: col = h*24 + k
#pragma unroll
    for (int k = 0; k < 24; k++) {
        pool[(2 * pp) * 49 + h * 24 + k]     = acc0[k];
        pool[(2 * pp + 1) * 49 + h * 24 + k] = acc1[k];
    }
    __syncthreads();

    {
        int mp = t & 63, cg = t >> 6;           // 64 pooled px x 4 channel groups
        int pr = mp >> 5, wc = mp & 31;         // pooled row (0/1), pooled col
        int p00 = pr * 128 + 2 * wc;            // local pixel indices
        int p01 = p00 + 1, p10 = p00 + 64, p11 = p00 + 65;
        int m = (hc * 2 + pr) * 32 + wc;        // global pooled index
#pragma unroll
        for (int j = 0; j < 10; j++) {
            int c48 = 8 + cg * 10 + j;          // pooled channels live in cols 8..47
            float v = fmaxf(fmaxf(pool[p00 * 49 + c48], pool[p01 * 49 + c48]),
                            fmaxf(pool[p10 * 49 + c48], pool[p11 * 49 + c48]));
            if (c48 < 16) {                     // phi channel c48-8
                __half hh, ll;
                split1h(v, hh, ll);
                size_t o = ((size_t)b * HWP + m) * CK + (c48 - 8);
                d_phih[o] = hh; d_phil[o] = ll;
            } else {                            // g channel c48-16 (fp16 single)
                size_t o = ((size_t)b * CV + (c48 - 16)) * HWP + m;
                d_gh[o] = __float2half_rn(v);
            }
        }
    }
}

// ---------------------------------------------------------------------------
// Kernel B: fp16 HMMA flash attention + fused output projection/residual.
// Online row max (conditional rescale). Softmax via ex2.approx.f16x2 (2 exps
// per MUFU; output is the GEMM2 A-fragment). Denominator computed by a 5th
// GEMM2 MMA against an all-ones B (every lane gets the full row sum; no shfl
// reduction). 9 MMAs / 16 keys. Split-K x2. grid (32,16), 512 threads.
// smem 96.5KB -> 2 CTAs/SM.
// ---------------------------------------------------------------------------
#define PHI_H 0
#define PHI_L 16384
#define G_H   32768
#define GSTRB 2064
#define PART  0                      /* overlays phi planes after main loop */
#define OS    32768                  /* o_s [128][34] floats, overlays g */
#define WS    (32768 + 128 * 34 * 4) /* w_s [32][64] floats */
#define SMEM_ATTN 98816

__global__ __launch_bounds__(512, 2) void attn_mma_kernel(
    const float* __restrict__ x,
    const float* __restrict__ w_o,
    const float* __restrict__ gamma_p,
    float* __restrict__ out)
{
    extern __shared__ char smem[];
    const int tid = threadIdx.x;
    const int lane = tid & 31;
    const int w = tid >> 5;        // 0..15
    const int wq = w & 7;          // query-set id
    const int team = w >> 3;       // 0/1 (key half)
    const int gid = lane >> 2;     // group id 0..7
    const int tig = lane & 3;      // thread in group
    const int b = blockIdx.y;
    const int q0 = blockIdx.x * 128;
    const uint32_t ONES = 0x3C003C00u;      // fp16x2 (1.0, 1.0)
    const float L2E = 1.4426950408889634f;  // log2(e)

    // fill phi planes (contiguous copy)
    {
        const uint4* ph = (const uint4*)(d_phih + (size_t)b * HWP * CK);
        const uint4* pl = (const uint4*)(d_phil + (size_t)b * HWP * CK);
        uint4* sh = (uint4*)(smem + PHI_H);
        uint4* sl = (uint4*)(smem + PHI_L);
        for (int i = tid; i < 1024; i += 512) { sh[i] = ph[i]; sl[i] = pl[i]; }
    }
    // fill g plane (32 rows x 2048B, padded stride 2064B)
    for (int i = tid; i < 4096; i += 512) {
        int c = i >> 7, j = i & 127;
        *(uint4*)(smem + G_H + c * GSTRB + j * 16) =
            *(const uint4*)(d_gh + ((size_t)b * CV + c) * HWP + j * 8);
    }

    // theta A fragments (constant across key loop)
    const int qb = q0 + wq * 16;
    const float* th = d_theta + (size_t)b * CK * HW;
    float t00 = th[(2 * tig) * HW + qb + gid];
    float t01 = th[(2 * tig + 1) * HW + qb + gid];
    float t10 = th[(2 * tig) * HW + qb + gid + 8];
    float t11 = th[(2 * tig + 1) * HW + qb + gid + 8];
    uint32_t ah0, al0, ah1, al1;
    split2h(t00, t01, ah0, al0);
    split2h(t10, t11, ah1, al1);
    __syncthreads();

    float o[4][4];
#pragma unroll
    for (int nf = 0; nf < 4; nf++)
#pragma unroll
        for (int j = 0; j < 4; j++) o[nf][j] = 0.f;
    float dn[4] = {0.f, 0.f, 0.f, 0.f};   // den accumulators (ones-MMA)
    float mx0 = -1e30f, mx1 = -1e30f;     // running row maxes
    float nmb0 = 0.f, nmb1 = 0.f;         // -mx * log2(e), updated on rescale

    const uint32_t phi_off = gid * 16 + tig * 4;
    const int m_start = team * 512;

#pragma unroll 2
    for (int m0 = m_start; m0 < m_start + 512; m0 += 16) {
        // ---- GEMM1 for 16 keys (two 8-key halves); exact 4-product split ----
        uint32_t bh0 = *(uint32_t*)(smem + PHI_H + m0 * 16 + phi_off);
        uint32_t bl0 = *(uint32_t*)(smem + PHI_L + m0 * 16 + phi_off);
        uint32_t bh1 = *(uint32_t*)(smem + PHI_H + (m0 + 8) * 16 + phi_off);
        uint32_t bl1 = *(uint32_t*)(smem + PHI_L + (m0 + 8) * 16 + phi_off);
        float sA0 = 0.f, sA1 = 0.f, sA2 = 0.f, sA3 = 0.f;
        float sB0 = 0.f, sB1 = 0.f, sB2 = 0.f, sB3 = 0.f;
        MMAH16816(sA0, sA1, sA2, sA3, ah0, ah1, al0, al1, bh0, bh0);
        MMAH16816(sA0, sA1, sA2, sA3, ah0, ah1, al0, al1, bl0, bl0);
        MMAH16816(sB0, sB1, sB2, sB3, ah0, ah1, al0, al1, bh1, bh1);
        MMAH16816(sB0, sB1, sB2, sB3, ah0, ah1, al0, al1, bl1, bl1);

        // ---- chunk row max (row gid: sA0,sA1,sB0,sB1; row gid+8: sA2,sA3,sB2,sB3)
        float c0 = fmaxf(fmaxf(sA0, sA1), fmaxf(sB0, sB1));
        float c1 = fmaxf(fmaxf(sA2, sA3), fmaxf(sB2, sB3));
        c0 = fmaxf(c0, __shfl_xor_sync(0xffffffffu, c0, 1));
        c0 = fmaxf(c0, __shfl_xor_sync(0xffffffffu, c0, 2));
        c1 = fmaxf(c1, __shfl_xor_sync(0xffffffffu, c1, 1));
        c1 = fmaxf(c1, __shfl_xor_sync(0xffffffffu, c1, 2));

        // ---- conditional rescale: only when some row's max grew (warp-uniform)
        if (__any_sync(0xffffffffu, (c0 > mx0) | (c1 > mx1))) {
            float nm0 = fmaxf(mx0, c0), nm1 = fmaxf(mx1, c1);
            float sc0 = __expf(mx0 - nm0), sc1 = __expf(mx1 - nm1);
            mx0 = nm0; mx1 = nm1;
            nmb0 = -nm0 * L2E; nmb1 = -nm1 * L2E;
            dn[0] *= sc0; dn[2] *= sc1;
#pragma unroll
            for (int nf = 0; nf < 4; nf++) {
                o[nf][0] *= sc0; o[nf][1] *= sc0;
                o[nf][2] *= sc1; o[nf][3] *= sc1;
            }
        }

        // ---- E = 2^(s*log2e - mx*log2e) via packed fp16x2 ex2 ----
        uint32_t Ah0 = ex2h2(pack2h(fmaf(sA0, L2E, nmb0), fmaf(sA1, L2E, nmb0)));
        uint32_t Ah1 = ex2h2(pack2h(fmaf(sA2, L2E, nmb1), fmaf(sA3, L2E, nmb1)));
        uint32_t Ah2 = ex2h2(pack2h(fmaf(sB0, L2E, nmb0), fmaf(sB1, L2E, nmb0)));
        uint32_t Ah3 = ex2h2(pack2h(fmaf(sB2, L2E, nmb1), fmaf(sB3, L2E, nmb1)));

        // ---- GEMM2: den (ones-B) + 4 channel blocks, 16 real keys ----
        MMAH16816(dn[0], dn[1], dn[2], dn[3], Ah0, Ah1, Ah2, Ah3, ONES, ONES);
        const uint32_t mo0 = (uint32_t)(m0 + 2 * tig) * 2 + gid * GSTRB;
        const uint32_t mo1 = mo0 + 16;
#pragma unroll
        for (int nf = 0; nf < 4; nf++) {
            const char* g_base = smem + G_H + nf * 8 * GSTRB;
            uint32_t b0 = *(uint32_t*)(g_base + mo0);
            uint32_t b1 = *(uint32_t*)(g_base + mo1);
            MMAH16816(o[nf][0], o[nf][1], o[nf][2], o[nf][3],
                      Ah0, Ah1, Ah2, Ah3, b0, b1);
        }
    }

    __syncthreads();   // phi + g planes dead; overlays become live

    // stage w_o transposed: w_s[c][ch] = w_o[ch][c]
    {
        float* w_s = (float*)(smem + WS);
        for (int i = tid; i < 2048; i += 512) {
            int ch = i >> 5, c = i & 31;
            w_s[c * 64 + ch] = w_o[i];
        }
    }

    // ---- split-K combine with max reconciliation ----
    if (team == 1) {
        float* pp = (float*)(smem + PART) + ((w - 8) * 32 + lane) * 20;
#pragma unroll
        for (int nf = 0; nf < 4; nf++)
#pragma unroll
            for (int j = 0; j < 4; j++) pp[nf * 4 + j] = o[nf][j];
        pp[16] = dn[0]; pp[17] = dn[2];
        pp[18] = mx0;   pp[19] = mx1;
    }
    __syncthreads();
    if (team == 0) {
        const float* pp = (const float*)(smem + PART) + (w * 32 + lane) * 20;
        float om0 = pp[18], om1 = pp[19];
        float gm0 = fmaxf(mx0, om0), gm1 = fmaxf(mx1, om1);
        float a0 = __expf(mx0 - gm0), b0s = __expf(om0 - gm0);
        float a1 = __expf(mx1 - gm1), b1s = __expf(om1 - gm1);
#pragma unroll
        for (int nf = 0; nf < 4; nf++) {
            o[nf][0] = o[nf][0] * a0 + pp[nf * 4 + 0] * b0s;
            o[nf][1] = o[nf][1] * a0 + pp[nf * 4 + 1] * b0s;
            o[nf][2] = o[nf][2] * a1 + pp[nf * 4 + 2] * b1s;
            o[nf][3] = o[nf][3] * a1 + pp[nf * 4 + 3] * b1s;
        }
        float den0 = dn[0] * a0 + pp[16] * b0s;
        float den1 = dn[2] * a1 + pp[17] * b1s;
        float i0 = 1.f / den0, i1 = 1.f / den1;

        // write normalized o to smem [q_local][c], stride 34 (float2-aligned)
        float* os = (float*)(smem + OS);
        int ql = wq * 16 + gid;
#pragma unroll
        for (int nf = 0; nf < 4; nf++) {
            int c = nf * 8 + 2 * tig;
            *(float2*)&os[ql * 34 + c]       = make_float2(o[nf][0] * i0, o[nf][1] * i0);
            *(float2*)&os[(ql + 8) * 34 + c] = make_float2(o[nf][2] * i1, o[nf][3] * i1);
        }
    }
    __syncthreads();

    // ---- fused output projection: out = gamma * (w_o @ o) + x ----
    {
        const float* os = (const float*)(smem + OS);
        const float* w_s = (const float*)(smem + WS);
        const float gamma = *gamma_p;
        int q = tid & 127, cg = tid >> 7;       // 128 queries x 4 ch-groups of 16
        float accf[16];
#pragma unroll
        for (int j = 0; j < 16; j++) accf[j] = 0.f;
        for (int c = 0; c < 32; c++) {
            float ov = os[q * 34 + c];
            const float4* wr = (const float4*)&w_s[c * 64 + cg * 16];
#pragma unroll
            for (int j4 = 0; j4 < 4; j4++) {
                float4 wq4 = wr[j4];
                accf[4 * j4]     += wq4.x * ov;
                accf[4 * j4 + 1] += wq4.y * ov;
                accf[4 * j4 + 2] += wq4.z * ov;
                accf[4 * j4 + 3] += wq4.w * ov;
            }
        }
        int p = q0 + q;
        const float* xb = x + (size_t)b * NC * HW + p;
        float* ob = out + (size_t)b * NC * HW + p;
#pragma unroll
        for (int j = 0; j < 16; j++) {
            int ch = cg * 16 + j;
            ob[(size_t)ch * HW] = gamma * accf[j] + xb[(size_t)ch * HW];
        }
    }
}

// ---------------------------------------------------------------------------
extern "C" void kernel_launch(void* const* d_in, const int* in_sizes, int n_in,
                              void* d_out, int out_size)
{
    const float* x       = (const float*)d_in[0];
    const float* w_theta = (const float*)d_in[1];
    const float* w_phi   = (const float*)d_in[2];
    const float* w_g     = (const float*)d_in[3];
    const float* w_o     = (const float*)d_in[4];
    const float* gamma_p = (const float*)d_in[5];
    float* out = (float*)d_out;

    cudaFuncSetAttribute(proj_kernel, cudaFuncAttributeMaxDynamicSharedMemorySize,
                         SMEM_PROJ);
    proj_kernel<<<dim3(16, 16), 256, SMEM_PROJ>>>(x, w_theta, w_phi, w_g);

    cudaFuncSetAttribute(attn_mma_kernel, cudaFuncAttributeMaxDynamicSharedMemorySize,
                         SMEM_ATTN);
    attn_mma_kernel<<<dim3(32, 16), 512, SMEM_ATTN>>>(x, w_o, gamma_p, out);
}